// round 1
// baseline (speedup 1.0000x reference)
#include <cuda_runtime.h>
#include <math.h>

#define B_    2
#define LF_   2048
#define TS_   512
#define D2_   512
#define H_    8
#define HD_   64
#define POOLH 2048

// ---------------------------------------------------------------------------
// Scratch (allocation-free rule: one big __device__ array, offsets below)
// ---------------------------------------------------------------------------
static const size_t O_Y     = 0;                       // (B,TS,512)    lift out
static const size_t O_QKV_F = O_Y     + 524288;        // (B*LF,1536)   fself qkv
static const size_t O_Q_FC  = O_QKV_F + 6291456;       // (B*LF,512)    fcross q
static const size_t O_KV_FC = O_Q_FC  + 2097152;       // (B*TS,1024)   fcross kv (dedup!)
static const size_t O_O1    = O_KV_FC + 1048576;       // (B*LF,512)    fself attn out
static const size_t O_O2    = O_O1    + 2097152;       // (B*LF,512)    fcross attn out
static const size_t O_H1    = O_O2    + 2097152;       // (B*TS,2048)   pool hidden
static const size_t O_S     = O_H1    + 2097152;       // (B,TS,512)    pool out
static const size_t O_SS    = O_S     + 524288;        // (B,TS,512)    shifted pool out
static const size_t O_QKV_S = O_SS    + 524288;        // (B*TS,1536)   sself qkv
static const size_t O_Q_SC  = O_QKV_S + 1572864;       // (B*TS,512)    scross q
static const size_t O_KV_SC = O_Q_SC  + 524288;        // (B*TS,1024)   scross kv
static const size_t O_O3    = O_KV_SC + 1048576;       // (B*TS,512)
static const size_t O_O4    = O_O3    + 524288;        // (B*TS,512)
static const size_t SCRATCH_FLOATS = O_O4 + 524288;    // 21,495,808 floats (~86MB)

__device__ float g_scratch[SCRATCH_FLOATS];

// ---------------------------------------------------------------------------
// Generic SGEMM: C[m, coff+n] = act( A[m, aoff+k] * W[k, woff+n] + bias[n] )
// Block tile 64x64, K-tile 16, 256 threads, 4x4 micro-tile.
// Requires: M%64==0, N%64==0, K%16==0, aoff/woff/coff %4==0, ld* %4==0.
// act: 0 = none, 1 = tanh-GELU (JAX default approximate gelu)
// ---------------------------------------------------------------------------
__global__ __launch_bounds__(256) void gemm_kernel(
    const float* __restrict__ A, int lda, int aoff,
    const float* __restrict__ W, int ldw, int woff,
    const float* __restrict__ bias,
    float* __restrict__ C, int ldc, int coff,
    int M, int N, int K, int act)
{
    __shared__ float As[16][64];
    __shared__ float Bs[16][68];

    const int tid = threadIdx.x;
    const int ty = tid >> 4, tx = tid & 15;
    const int m0 = blockIdx.y * 64, n0 = blockIdx.x * 64;

    const int arow = tid >> 2, ac4 = tid & 3;    // A tile: 64 rows x 4 float4
    const int brow = tid >> 4, bc4 = tid & 15;   // B tile: 16 rows x 16 float4

    float acc[4][4] = {};

    for (int k0 = 0; k0 < K; k0 += 16) {
        float4 a4 = *(const float4*)(A + (size_t)(m0 + arow) * lda + aoff + k0 + ac4 * 4);
        float4 b4 = *(const float4*)(W + (size_t)(k0 + brow) * ldw + woff + n0 + bc4 * 4);
        __syncthreads();
        As[ac4 * 4 + 0][arow] = a4.x;
        As[ac4 * 4 + 1][arow] = a4.y;
        As[ac4 * 4 + 2][arow] = a4.z;
        As[ac4 * 4 + 3][arow] = a4.w;
        *(float4*)&Bs[brow][bc4 * 4] = b4;
        __syncthreads();
        #pragma unroll
        for (int kk = 0; kk < 16; kk++) {
            float4 av = *(const float4*)&As[kk][ty * 4];
            float4 bv = *(const float4*)&Bs[kk][tx * 4];
            float aa[4] = {av.x, av.y, av.z, av.w};
            float bb[4] = {bv.x, bv.y, bv.z, bv.w};
            #pragma unroll
            for (int i = 0; i < 4; i++)
                #pragma unroll
                for (int j = 0; j < 4; j++)
                    acc[i][j] += aa[i] * bb[j];
        }
    }

    #pragma unroll
    for (int i = 0; i < 4; i++) {
        const int m = m0 + ty * 4 + i;
        float o[4];
        #pragma unroll
        for (int j = 0; j < 4; j++) {
            const int n = n0 + tx * 4 + j;
            float v = acc[i][j] + bias[n];
            if (act == 1) {
                float u = 0.7978845608028654f * (v + 0.044715f * v * v * v);
                v = 0.5f * v * (1.0f + tanhf(u));
            }
            o[j] = v;
        }
        *(float4*)(C + (size_t)m * ldc + coff + n0 + tx * 4) =
            make_float4(o[0], o[1], o[2], o[3]);
    }
}

// ---------------------------------------------------------------------------
// Flash attention (fp32, online softmax). hd=64, H heads interleaved at h*64.
// Grid: (Tq/64, H, B). 256 threads, 64 q-rows per block, 64-key tiles.
// Q/K/V/O addressed as buf[(b*T + t)*ld + off + h*64 + d].
// Requires Tq%64==0, Tk%64==0.
// ---------------------------------------------------------------------------
#define SMEM_ATTN (4 * 64 * 68 * 4)

__global__ __launch_bounds__(256) void attn_kernel(
    const float* __restrict__ Q, int ldq, int qoff,
    const float* __restrict__ Kp, int ldk, int koff,
    const float* __restrict__ Vp, int ldv, int voff,
    float* __restrict__ O, int ldo, int ooff,
    int Tq, int Tk, float scale)
{
    extern __shared__ float sm[];
    float (*QsT)[68] = (float(*)[68])(sm);             // [dim][qrow]
    float (*KsT)[68] = (float(*)[68])(sm + 64 * 68);   // [dim][key]
    float (*Vs )[68] = (float(*)[68])(sm + 2 * 64 * 68); // [key][dim]
    float (*PsT)[68] = (float(*)[68])(sm + 3 * 64 * 68); // [key][qrow]

    const int tid = threadIdx.x;
    const int ty = tid >> 4, tx = tid & 15;
    const int b = blockIdx.z, h = blockIdx.y, qt = blockIdx.x;

    const float* Qb = Q  + (size_t)(b * Tq + qt * 64) * ldq + qoff + h * HD_;
    const float* Kb = Kp + (size_t)(b * Tk) * ldk + koff + h * HD_;
    const float* Vb = Vp + (size_t)(b * Tk) * ldv + voff + h * HD_;

    // load Q tile, transposed & pre-scaled
    for (int e = tid; e < 64 * 16; e += 256) {
        const int r = e >> 4, c4 = e & 15;
        float4 q4 = *(const float4*)(Qb + (size_t)r * ldq + c4 * 4);
        QsT[c4 * 4 + 0][r] = q4.x * scale;
        QsT[c4 * 4 + 1][r] = q4.y * scale;
        QsT[c4 * 4 + 2][r] = q4.z * scale;
        QsT[c4 * 4 + 3][r] = q4.w * scale;
    }

    float m_i[4], l_i[4], acc[4][4];
    #pragma unroll
    for (int i = 0; i < 4; i++) {
        m_i[i] = -1e30f; l_i[i] = 0.f;
        #pragma unroll
        for (int j = 0; j < 4; j++) acc[i][j] = 0.f;
    }

    for (int kt = 0; kt < Tk; kt += 64) {
        __syncthreads();  // protect prior-iter reads of KsT/Vs (also covers Q load, iter 0)
        for (int e = tid; e < 64 * 16; e += 256) {
            const int r = e >> 4, c4 = e & 15;
            float4 k4 = *(const float4*)(Kb + (size_t)(kt + r) * ldk + c4 * 4);
            KsT[c4 * 4 + 0][r] = k4.x;
            KsT[c4 * 4 + 1][r] = k4.y;
            KsT[c4 * 4 + 2][r] = k4.z;
            KsT[c4 * 4 + 3][r] = k4.w;
            float4 v4 = *(const float4*)(Vb + (size_t)(kt + r) * ldv + c4 * 4);
            *(float4*)&Vs[r][c4 * 4] = v4;
        }
        __syncthreads();

        // S = Q K^T (4x4 per thread; rows ty*4.., keys tx*4..)
        float s[4][4] = {};
        #pragma unroll
        for (int kk = 0; kk < 64; kk++) {
            float4 qv = *(const float4*)&QsT[kk][ty * 4];
            float4 kv = *(const float4*)&KsT[kk][tx * 4];
            float qa[4] = {qv.x, qv.y, qv.z, qv.w};
            float ka[4] = {kv.x, kv.y, kv.z, kv.w};
            #pragma unroll
            for (int i = 0; i < 4; i++)
                #pragma unroll
                for (int j = 0; j < 4; j++)
                    s[i][j] += qa[i] * ka[j];
        }

        // online softmax (row groups = 16 consecutive lanes -> shfl_xor 8..1)
        #pragma unroll
        for (int i = 0; i < 4; i++) {
            float rm = fmaxf(fmaxf(s[i][0], s[i][1]), fmaxf(s[i][2], s[i][3]));
            #pragma unroll
            for (int off = 8; off > 0; off >>= 1)
                rm = fmaxf(rm, __shfl_xor_sync(0xffffffffu, rm, off));
            const float mn = fmaxf(m_i[i], rm);
            const float corr = __expf(m_i[i] - mn);
            float rs = 0.f;
            #pragma unroll
            for (int j = 0; j < 4; j++) {
                float p = __expf(s[i][j] - mn);
                s[i][j] = p;
                rs += p;
            }
            #pragma unroll
            for (int off = 8; off > 0; off >>= 1)
                rs += __shfl_xor_sync(0xffffffffu, rs, off);
            l_i[i] = l_i[i] * corr + rs;
            m_i[i] = mn;
            #pragma unroll
            for (int j = 0; j < 4; j++) acc[i][j] *= corr;
            #pragma unroll
            for (int j = 0; j < 4; j++) PsT[tx * 4 + j][ty * 4 + i] = s[i][j];
        }
        __syncthreads();

        // O += P V
        #pragma unroll
        for (int jj = 0; jj < 64; jj++) {
            float4 pv = *(const float4*)&PsT[jj][ty * 4];
            float4 vv = *(const float4*)&Vs[jj][tx * 4];
            float pa[4] = {pv.x, pv.y, pv.z, pv.w};
            float va[4] = {vv.x, vv.y, vv.z, vv.w};
            #pragma unroll
            for (int i = 0; i < 4; i++)
                #pragma unroll
                for (int j = 0; j < 4; j++)
                    acc[i][j] += pa[i] * va[j];
        }
    }

    float* Ob = O + (size_t)(b * Tq + qt * 64) * ldo + ooff + h * HD_;
    #pragma unroll
    for (int i = 0; i < 4; i++) {
        const float inv = 1.0f / l_i[i];
        *(float4*)(Ob + (size_t)(ty * 4 + i) * ldo + tx * 4) =
            make_float4(acc[i][0] * inv, acc[i][1] * inv,
                        acc[i][2] * inv, acc[i][3] * inv);
    }
}

// ---------------------------------------------------------------------------
// Shifted copy for slow path: dst[b,0,:]=0 ; dst[b,t,:]=src[b,t-1,:]
// ---------------------------------------------------------------------------
__global__ void shift_kernel(const float* __restrict__ src, float* __restrict__ dst)
{
    const int e = blockIdx.x * 256 + threadIdx.x;
    if (e >= B_ * TS_ * D2_) return;
    const int t = (e / D2_) % TS_;
    dst[e] = (t == 0) ? 0.f : src[e - D2_];
}

// ---------------------------------------------------------------------------
// Host orchestration
// ---------------------------------------------------------------------------
extern "C" void kernel_launch(void* const* d_in, const int* in_sizes, int n_in,
                              void* d_out, int out_size)
{
    (void)in_sizes; (void)n_in; (void)out_size;

    const float* x_fast      = (const float*)d_in[0];
    const float* x_slow      = (const float*)d_in[1];
    const float* fself_wqkv  = (const float*)d_in[2];
    const float* fself_bqkv  = (const float*)d_in[3];
    const float* fself_wo    = (const float*)d_in[4];
    const float* fself_bo    = (const float*)d_in[5];
    const float* fcross_wqkv = (const float*)d_in[6];
    const float* fcross_bqkv = (const float*)d_in[7];
    const float* fcross_wo   = (const float*)d_in[8];
    const float* fcross_bo   = (const float*)d_in[9];
    const float* sself_wqkv  = (const float*)d_in[10];
    const float* sself_bqkv  = (const float*)d_in[11];
    const float* sself_wo    = (const float*)d_in[12];
    const float* sself_bo    = (const float*)d_in[13];
    const float* scross_wqkv = (const float*)d_in[14];
    const float* scross_bqkv = (const float*)d_in[15];
    const float* scross_wo   = (const float*)d_in[16];
    const float* scross_bo   = (const float*)d_in[17];
    const float* lift_w      = (const float*)d_in[18];
    const float* lift_b      = (const float*)d_in[19];
    const float* pool_w1     = (const float*)d_in[20];
    const float* pool_b1     = (const float*)d_in[21];
    const float* pool_w2     = (const float*)d_in[22];
    const float* pool_b2     = (const float*)d_in[23];

    float* out = (float*)d_out;
    float* zf = out;                                 // (B, LF, 1024)
    float* zs = out + (size_t)B_ * LF_ * 1024;       // (B, TS, 1024)

    float* S0 = nullptr;
    cudaGetSymbolAddress((void**)&S0, g_scratch);
    float* y     = S0 + O_Y;
    float* qkv_f = S0 + O_QKV_F;
    float* q_fc  = S0 + O_Q_FC;
    float* kv_fc = S0 + O_KV_FC;
    float* o1    = S0 + O_O1;
    float* o2    = S0 + O_O2;
    float* h1    = S0 + O_H1;
    float* s     = S0 + O_S;
    float* ss    = S0 + O_SS;
    float* qkv_s = S0 + O_QKV_S;
    float* q_sc  = S0 + O_Q_SC;
    float* kv_sc = S0 + O_KV_SC;
    float* o3    = S0 + O_O3;
    float* o4    = S0 + O_O4;

    cudaFuncSetAttribute(attn_kernel,
                         cudaFuncAttributeMaxDynamicSharedMemorySize, SMEM_ATTN);

    const float scale = 0.125f;  // 1/sqrt(64)

    // 1) lift: y = x_slow @ lift_w + lift_b            (1024 x 512, K=1024)
    gemm_kernel<<<dim3(8, 16), 256>>>(x_slow, 1024, 0, lift_w, 512, 0, lift_b,
                                      y, 512, 0, 1024, 512, 1024, 0);
    // 2) fself qkv: x1 @ fself_wqkv                    (4096 x 1536, K=512)
    gemm_kernel<<<dim3(24, 64), 256>>>(x_fast, 1024, 0, fself_wqkv, 1536, 0, fself_bqkv,
                                       qkv_f, 1536, 0, 4096, 1536, 512, 0);
    // 3) fcross q: x2 @ fcross_wqkv[:, :512]           (4096 x 512, K=512)
    gemm_kernel<<<dim3(8, 64), 256>>>(x_fast, 1024, 512, fcross_wqkv, 1536, 0, fcross_bqkv,
                                      q_fc, 512, 0, 4096, 512, 512, 0);
    // 4) fcross kv on DEDUPED y (TS rows): y @ fcross_wqkv[:, 512:]  (1024 x 1024, K=512)
    gemm_kernel<<<dim3(16, 16), 256>>>(y, 512, 0, fcross_wqkv, 1536, 512, fcross_bqkv + 512,
                                       kv_fc, 1024, 0, 1024, 1024, 512, 0);
    // 9) pool MLP layer 1 (+tanh GELU): (1024 x 2048, K=4096)  [independent: issue early]
    gemm_kernel<<<dim3(32, 16), 256>>>(x_fast, 4096, 0, pool_w1, 2048, 0, pool_b1,
                                       h1, 2048, 0, 1024, POOLH, 4096, 1);
    // 5) fself attention (Tq=Tk=2048)
    attn_kernel<<<dim3(32, H_, B_), 256, SMEM_ATTN>>>(
        qkv_f, 1536, 0, qkv_f, 1536, 512, qkv_f, 1536, 1024,
        o1, 512, 0, LF_, LF_, scale);
    // 6) fcross attention (Tq=2048, Tk=512 — repeat folded out, exact)
    attn_kernel<<<dim3(32, H_, B_), 256, SMEM_ATTN>>>(
        q_fc, 512, 0, kv_fc, 1024, 0, kv_fc, 1024, 512,
        o2, 512, 0, LF_, TS_, scale);
    // 7) fself out-proj -> z_fast[:, :512]
    gemm_kernel<<<dim3(8, 64), 256>>>(o1, 512, 0, fself_wo, 512, 0, fself_bo,
                                      zf, 1024, 0, 4096, 512, 512, 0);
    // 8) fcross out-proj -> z_fast[:, 512:]
    gemm_kernel<<<dim3(8, 64), 256>>>(o2, 512, 0, fcross_wo, 512, 0, fcross_bo,
                                      zf, 1024, 512, 4096, 512, 512, 0);
    // 10) pool MLP layer 2: (1024 x 512, K=2048)
    gemm_kernel<<<dim3(8, 16), 256>>>(h1, 2048, 0, pool_w2, 512, 0, pool_b2,
                                      s, 512, 0, 1024, 512, 2048, 0);
    // 11) shift s by one slow step (zeros at t=0)
    shift_kernel<<<(B_ * TS_ * D2_ + 255) / 256, 256>>>(s, ss);
    // 12) sself qkv: s1 @ sself_wqkv                   (1024 x 1536, K=512)
    gemm_kernel<<<dim3(24, 16), 256>>>(x_slow, 1024, 0, sself_wqkv, 1536, 0, sself_bqkv,
                                       qkv_s, 1536, 0, 1024, 1536, 512, 0);
    // 13) scross q: s2 @ scross_wqkv[:, :512]
    gemm_kernel<<<dim3(8, 16), 256>>>(x_slow, 1024, 512, scross_wqkv, 1536, 0, scross_bqkv,
                                      q_sc, 512, 0, 1024, 512, 512, 0);
    // 14) scross kv: ss @ scross_wqkv[:, 512:]
    gemm_kernel<<<dim3(16, 16), 256>>>(ss, 512, 0, scross_wqkv, 1536, 512, scross_bqkv + 512,
                                       kv_sc, 1024, 0, 1024, 1024, 512, 0);
    // 15) sself attention (Tq=Tk=512)
    attn_kernel<<<dim3(8, H_, B_), 256, SMEM_ATTN>>>(
        qkv_s, 1536, 0, qkv_s, 1536, 512, qkv_s, 1536, 1024,
        o3, 512, 0, TS_, TS_, scale);
    // 16) scross attention (Tq=Tk=512)
    attn_kernel<<<dim3(8, H_, B_), 256, SMEM_ATTN>>>(
        q_sc, 512, 0, kv_sc, 1024, 0, kv_sc, 1024, 512,
        o4, 512, 0, TS_, TS_, scale);
    // 17) sself out-proj -> z_slow[:, :512]
    gemm_kernel<<<dim3(8, 16), 256>>>(o3, 512, 0, sself_wo, 512, 0, sself_bo,
                                      zs, 1024, 0, 1024, 512, 512, 0);
    // 18) scross out-proj -> z_slow[:, 512:]
    gemm_kernel<<<dim3(8, 16), 256>>>(o4, 512, 0, scross_wo, 512, 0, scross_bo,
                                      zs, 1024, 512, 1024, 512, 512, 0);
}

// round 2
// speedup vs baseline: 1.0232x; 1.0232x over previous
#include <cuda_runtime.h>
#include <math.h>

#define B_    2
#define LF_   2048
#define TS_   512
#define D2_   512
#define H_    8
#define HD_   64
#define POOLH 2048

typedef unsigned long long u64;

// ---------------------------------------------------------------------------
// Packed f32x2 helpers (Blackwell FFMA2 path — ptxas never emits this from C++)
// ---------------------------------------------------------------------------
__device__ __forceinline__ u64 dup2(float x) {
    u64 r;
    asm("mov.b64 %0, {%1, %1};" : "=l"(r) : "f"(x));
    return r;
}
__device__ __forceinline__ u64 pack2(float x, float y) {
    u64 r;
    asm("mov.b64 %0, {%1, %2};" : "=l"(r) : "f"(x), "f"(y));
    return r;
}
__device__ __forceinline__ void unpack2(u64 v, float &x, float &y) {
    asm("mov.b64 {%0, %1}, %2;" : "=f"(x), "=f"(y) : "l"(v));
}
__device__ __forceinline__ void ffma2(u64 &acc, u64 a, u64 b) {
    asm("fma.rn.f32x2 %0, %1, %2, %0;" : "+l"(acc) : "l"(a), "l"(b));
}
__device__ __forceinline__ void fmul2(u64 &acc, u64 m) {
    asm("mul.rn.f32x2 %0, %0, %1;" : "+l"(acc) : "l"(m));
}

// ---------------------------------------------------------------------------
// Scratch (allocation-free rule: one big __device__ array, offsets below)
// ---------------------------------------------------------------------------
static const size_t O_Y     = 0;                       // (B,TS,512)    lift out
static const size_t O_QKV_F = O_Y     + 524288;        // (B*LF,1536)   fself qkv
static const size_t O_Q_FC  = O_QKV_F + 6291456;       // (B*LF,512)    fcross q
static const size_t O_KV_FC = O_Q_FC  + 2097152;       // (B*TS,1024)   fcross kv (dedup!)
static const size_t O_O1    = O_KV_FC + 1048576;       // (B*LF,512)    fself attn out
static const size_t O_O2    = O_O1    + 2097152;       // (B*LF,512)    fcross attn out
static const size_t O_H1    = O_O2    + 2097152;       // (B*TS,2048)   pool hidden
static const size_t O_S     = O_H1    + 2097152;       // (B,TS,512)    pool out
static const size_t O_SS    = O_S     + 524288;        // (B,TS,512)    shifted pool out
static const size_t O_QKV_S = O_SS    + 524288;        // (B*TS,1536)   sself qkv
static const size_t O_Q_SC  = O_QKV_S + 1572864;       // (B*TS,512)    scross q
static const size_t O_KV_SC = O_Q_SC  + 524288;        // (B*TS,1024)   scross kv
static const size_t O_O3    = O_KV_SC + 1048576;       // (B*TS,512)
static const size_t O_O4    = O_O3    + 524288;        // (B*TS,512)
static const size_t SCRATCH_FLOATS = O_O4 + 524288;

__device__ float g_scratch[SCRATCH_FLOATS];

// ---------------------------------------------------------------------------
// Generic SGEMM: C[m, coff+n] = act( A[m, aoff+k] * W[k, woff+n] + bias[n] )
// Block tile 64x64, K-tile 16, 256 threads, 4x4 micro-tile, FFMA2 inner loop.
// act: 0 = none, 1 = tanh-GELU
// ---------------------------------------------------------------------------
__global__ __launch_bounds__(256) void gemm_kernel(
    const float* __restrict__ A, int lda, int aoff,
    const float* __restrict__ W, int ldw, int woff,
    const float* __restrict__ bias,
    float* __restrict__ C, int ldc, int coff,
    int M, int N, int K, int act)
{
    __shared__ float As[16][64];   // [k][m] — m contiguous -> free b64 pair loads
    __shared__ float Bs[16][68];

    const int tid = threadIdx.x;
    const int ty = tid >> 4, tx = tid & 15;
    const int m0 = blockIdx.y * 64, n0 = blockIdx.x * 64;

    const int arow = tid >> 2, ac4 = tid & 3;    // A tile: 64 rows x 4 float4
    const int brow = tid >> 4, bc4 = tid & 15;   // B tile: 16 rows x 16 float4

    u64 acc2[2][4] = {};   // [i-pair][j] packed (row 2p, row 2p+1)

    for (int k0 = 0; k0 < K; k0 += 16) {
        float4 a4 = *(const float4*)(A + (size_t)(m0 + arow) * lda + aoff + k0 + ac4 * 4);
        float4 b4 = *(const float4*)(W + (size_t)(k0 + brow) * ldw + woff + n0 + bc4 * 4);
        __syncthreads();
        As[ac4 * 4 + 0][arow] = a4.x;
        As[ac4 * 4 + 1][arow] = a4.y;
        As[ac4 * 4 + 2][arow] = a4.z;
        As[ac4 * 4 + 3][arow] = a4.w;
        *(float4*)&Bs[brow][bc4 * 4] = b4;
        __syncthreads();
        #pragma unroll
        for (int kk = 0; kk < 16; kk++) {
            u64 a01 = *(const u64*)&As[kk][ty * 4];
            u64 a23 = *(const u64*)&As[kk][ty * 4 + 2];
            float4 bv = *(const float4*)&Bs[kk][tx * 4];
            u64 b0 = dup2(bv.x), b1 = dup2(bv.y), b2 = dup2(bv.z), b3 = dup2(bv.w);
            ffma2(acc2[0][0], a01, b0);
            ffma2(acc2[0][1], a01, b1);
            ffma2(acc2[0][2], a01, b2);
            ffma2(acc2[0][3], a01, b3);
            ffma2(acc2[1][0], a23, b0);
            ffma2(acc2[1][1], a23, b1);
            ffma2(acc2[1][2], a23, b2);
            ffma2(acc2[1][3], a23, b3);
        }
    }

    #pragma unroll
    for (int p = 0; p < 2; p++) {
        float r0[4], r1[4];
        #pragma unroll
        for (int j = 0; j < 4; j++) unpack2(acc2[p][j], r0[j], r1[j]);
        #pragma unroll
        for (int half = 0; half < 2; half++) {
            float* r = half ? r1 : r0;
            const int m = m0 + ty * 4 + p * 2 + half;
            float o[4];
            #pragma unroll
            for (int j = 0; j < 4; j++) {
                const int n = n0 + tx * 4 + j;
                float v = r[j] + bias[n];
                if (act == 1) {
                    float u = 0.7978845608028654f * (v + 0.044715f * v * v * v);
                    v = 0.5f * v * (1.0f + tanhf(u));
                }
                o[j] = v;
            }
            *(float4*)(C + (size_t)m * ldc + coff + n0 + tx * 4) =
                make_float4(o[0], o[1], o[2], o[3]);
        }
    }
}

// ---------------------------------------------------------------------------
// Flash attention (fp32, online softmax, FFMA2 inner loops). hd=64.
// Grid: (Tq/64, H, B). 256 threads, 64 q-rows per block, 64-key tiles.
// ---------------------------------------------------------------------------
#define SMEM_ATTN (4 * 64 * 68 * 4)

__global__ __launch_bounds__(256) void attn_kernel(
    const float* __restrict__ Q, int ldq, int qoff,
    const float* __restrict__ Kp, int ldk, int koff,
    const float* __restrict__ Vp, int ldv, int voff,
    float* __restrict__ O, int ldo, int ooff,
    int Tq, int Tk, float scale)
{
    extern __shared__ float sm[];
    float (*QsT)[68] = (float(*)[68])(sm);               // [dim][qrow]
    float (*KsT)[68] = (float(*)[68])(sm + 64 * 68);     // [dim][key]
    float (*Vs )[68] = (float(*)[68])(sm + 2 * 64 * 68); // [key][dim]
    float (*PsT)[68] = (float(*)[68])(sm + 3 * 64 * 68); // [key][qrow]

    const int tid = threadIdx.x;
    const int ty = tid >> 4, tx = tid & 15;
    const int b = blockIdx.z, h = blockIdx.y, qt = blockIdx.x;

    const float* Qb = Q  + (size_t)(b * Tq + qt * 64) * ldq + qoff + h * HD_;
    const float* Kb = Kp + (size_t)(b * Tk) * ldk + koff + h * HD_;
    const float* Vb = Vp + (size_t)(b * Tk) * ldv + voff + h * HD_;

    for (int e = tid; e < 64 * 16; e += 256) {
        const int r = e >> 4, c4 = e & 15;
        float4 q4 = *(const float4*)(Qb + (size_t)r * ldq + c4 * 4);
        QsT[c4 * 4 + 0][r] = q4.x * scale;
        QsT[c4 * 4 + 1][r] = q4.y * scale;
        QsT[c4 * 4 + 2][r] = q4.z * scale;
        QsT[c4 * 4 + 3][r] = q4.w * scale;
    }

    float m_i[4], l_i[4];
    u64 acc2[2][4];   // O accumulator, packed pairs along q-row
    #pragma unroll
    for (int i = 0; i < 4; i++) { m_i[i] = -1e30f; l_i[i] = 0.f; }
    #pragma unroll
    for (int p = 0; p < 2; p++)
        #pragma unroll
        for (int j = 0; j < 4; j++) acc2[p][j] = 0ull;

    for (int kt = 0; kt < Tk; kt += 64) {
        __syncthreads();
        for (int e = tid; e < 64 * 16; e += 256) {
            const int r = e >> 4, c4 = e & 15;
            float4 k4 = *(const float4*)(Kb + (size_t)(kt + r) * ldk + c4 * 4);
            KsT[c4 * 4 + 0][r] = k4.x;
            KsT[c4 * 4 + 1][r] = k4.y;
            KsT[c4 * 4 + 2][r] = k4.z;
            KsT[c4 * 4 + 3][r] = k4.w;
            float4 v4 = *(const float4*)(Vb + (size_t)(kt + r) * ldv + c4 * 4);
            *(float4*)&Vs[r][c4 * 4] = v4;
        }
        __syncthreads();

        // S = Q K^T — packed pairs along q-row
        u64 s2[2][4] = {};
        #pragma unroll
        for (int kk = 0; kk < 64; kk++) {
            u64 q01 = *(const u64*)&QsT[kk][ty * 4];
            u64 q23 = *(const u64*)&QsT[kk][ty * 4 + 2];
            float4 kv = *(const float4*)&KsT[kk][tx * 4];
            u64 b0 = dup2(kv.x), b1 = dup2(kv.y), b2 = dup2(kv.z), b3 = dup2(kv.w);
            ffma2(s2[0][0], q01, b0);
            ffma2(s2[0][1], q01, b1);
            ffma2(s2[0][2], q01, b2);
            ffma2(s2[0][3], q01, b3);
            ffma2(s2[1][0], q23, b0);
            ffma2(s2[1][1], q23, b1);
            ffma2(s2[1][2], q23, b2);
            ffma2(s2[1][3], q23, b3);
        }
        float s[4][4];
        #pragma unroll
        for (int p = 0; p < 2; p++)
            #pragma unroll
            for (int j = 0; j < 4; j++) unpack2(s2[p][j], s[2 * p][j], s[2 * p + 1][j]);

        // online softmax
        float corr[4];
        #pragma unroll
        for (int i = 0; i < 4; i++) {
            float rm = fmaxf(fmaxf(s[i][0], s[i][1]), fmaxf(s[i][2], s[i][3]));
            #pragma unroll
            for (int off = 8; off > 0; off >>= 1)
                rm = fmaxf(rm, __shfl_xor_sync(0xffffffffu, rm, off));
            const float mn = fmaxf(m_i[i], rm);
            corr[i] = __expf(m_i[i] - mn);
            float rs = 0.f;
            #pragma unroll
            for (int j = 0; j < 4; j++) {
                float p = __expf(s[i][j] - mn);
                s[i][j] = p;
                rs += p;
            }
            #pragma unroll
            for (int off = 8; off > 0; off >>= 1)
                rs += __shfl_xor_sync(0xffffffffu, rs, off);
            l_i[i] = l_i[i] * corr[i] + rs;
            m_i[i] = mn;
            #pragma unroll
            for (int j = 0; j < 4; j++) PsT[tx * 4 + j][ty * 4 + i] = s[i][j];
        }
        #pragma unroll
        for (int p = 0; p < 2; p++) {
            u64 c = pack2(corr[2 * p], corr[2 * p + 1]);
            #pragma unroll
            for (int j = 0; j < 4; j++) fmul2(acc2[p][j], c);
        }
        __syncthreads();

        // O += P V — packed pairs along q-row
        #pragma unroll
        for (int jj = 0; jj < 64; jj++) {
            u64 p01 = *(const u64*)&PsT[jj][ty * 4];
            u64 p23 = *(const u64*)&PsT[jj][ty * 4 + 2];
            float4 vv = *(const float4*)&Vs[jj][tx * 4];
            u64 b0 = dup2(vv.x), b1 = dup2(vv.y), b2 = dup2(vv.z), b3 = dup2(vv.w);
            ffma2(acc2[0][0], p01, b0);
            ffma2(acc2[0][1], p01, b1);
            ffma2(acc2[0][2], p01, b2);
            ffma2(acc2[0][3], p01, b3);
            ffma2(acc2[1][0], p23, b0);
            ffma2(acc2[1][1], p23, b1);
            ffma2(acc2[1][2], p23, b2);
            ffma2(acc2[1][3], p23, b3);
        }
    }

    float* Ob = O + (size_t)(b * Tq + qt * 64) * ldo + ooff + h * HD_;
    #pragma unroll
    for (int p = 0; p < 2; p++) {
        float r0[4], r1[4];
        #pragma unroll
        for (int j = 0; j < 4; j++) unpack2(acc2[p][j], r0[j], r1[j]);
        const float inv0 = 1.0f / l_i[2 * p];
        const float inv1 = 1.0f / l_i[2 * p + 1];
        *(float4*)(Ob + (size_t)(ty * 4 + 2 * p) * ldo + tx * 4) =
            make_float4(r0[0] * inv0, r0[1] * inv0, r0[2] * inv0, r0[3] * inv0);
        *(float4*)(Ob + (size_t)(ty * 4 + 2 * p + 1) * ldo + tx * 4) =
            make_float4(r1[0] * inv1, r1[1] * inv1, r1[2] * inv1, r1[3] * inv1);
    }
}

// ---------------------------------------------------------------------------
// Shifted copy for slow path: dst[b,0,:]=0 ; dst[b,t,:]=src[b,t-1,:]
// ---------------------------------------------------------------------------
__global__ void shift_kernel(const float* __restrict__ src, float* __restrict__ dst)
{
    const int e = blockIdx.x * 256 + threadIdx.x;
    if (e >= B_ * TS_ * D2_) return;
    const int t = (e / D2_) % TS_;
    dst[e] = (t == 0) ? 0.f : src[e - D2_];
}

// ---------------------------------------------------------------------------
// Host orchestration
// ---------------------------------------------------------------------------
extern "C" void kernel_launch(void* const* d_in, const int* in_sizes, int n_in,
                              void* d_out, int out_size)
{
    (void)in_sizes; (void)n_in; (void)out_size;

    const float* x_fast      = (const float*)d_in[0];
    const float* x_slow      = (const float*)d_in[1];
    const float* fself_wqkv  = (const float*)d_in[2];
    const float* fself_bqkv  = (const float*)d_in[3];
    const float* fself_wo    = (const float*)d_in[4];
    const float* fself_bo    = (const float*)d_in[5];
    const float* fcross_wqkv = (const float*)d_in[6];
    const float* fcross_bqkv = (const float*)d_in[7];
    const float* fcross_wo   = (const float*)d_in[8];
    const float* fcross_bo   = (const float*)d_in[9];
    const float* sself_wqkv  = (const float*)d_in[10];
    const float* sself_bqkv  = (const float*)d_in[11];
    const float* sself_wo    = (const float*)d_in[12];
    const float* sself_bo    = (const float*)d_in[13];
    const float* scross_wqkv = (const float*)d_in[14];
    const float* scross_bqkv = (const float*)d_in[15];
    const float* scross_wo   = (const float*)d_in[16];
    const float* scross_bo   = (const float*)d_in[17];
    const float* lift_w      = (const float*)d_in[18];
    const float* lift_b      = (const float*)d_in[19];
    const float* pool_w1     = (const float*)d_in[20];
    const float* pool_b1     = (const float*)d_in[21];
    const float* pool_w2     = (const float*)d_in[22];
    const float* pool_b2     = (const float*)d_in[23];

    float* out = (float*)d_out;
    float* zf = out;                                 // (B, LF, 1024)
    float* zs = out + (size_t)B_ * LF_ * 1024;       // (B, TS, 1024)

    float* S0 = nullptr;
    cudaGetSymbolAddress((void**)&S0, g_scratch);
    float* y     = S0 + O_Y;
    float* qkv_f = S0 + O_QKV_F;
    float* q_fc  = S0 + O_Q_FC;
    float* kv_fc = S0 + O_KV_FC;
    float* o1    = S0 + O_O1;
    float* o2    = S0 + O_O2;
    float* h1    = S0 + O_H1;
    float* s     = S0 + O_S;
    float* ss    = S0 + O_SS;
    float* qkv_s = S0 + O_QKV_S;
    float* q_sc  = S0 + O_Q_SC;
    float* kv_sc = S0 + O_KV_SC;
    float* o3    = S0 + O_O3;
    float* o4    = S0 + O_O4;

    cudaFuncSetAttribute(attn_kernel,
                         cudaFuncAttributeMaxDynamicSharedMemorySize, SMEM_ATTN);

    const float scale = 0.125f;  // 1/sqrt(64)

    // 1) lift: y = x_slow @ lift_w + lift_b            (1024 x 512, K=1024)
    gemm_kernel<<<dim3(8, 16), 256>>>(x_slow, 1024, 0, lift_w, 512, 0, lift_b,
                                      y, 512, 0, 1024, 512, 1024, 0);
    // 2) fself qkv: x1 @ fself_wqkv                    (4096 x 1536, K=512)
    gemm_kernel<<<dim3(24, 64), 256>>>(x_fast, 1024, 0, fself_wqkv, 1536, 0, fself_bqkv,
                                       qkv_f, 1536, 0, 4096, 1536, 512, 0);
    // 3) fcross q: x2 @ fcross_wqkv[:, :512]           (4096 x 512, K=512)
    gemm_kernel<<<dim3(8, 64), 256>>>(x_fast, 1024, 512, fcross_wqkv, 1536, 0, fcross_bqkv,
                                      q_fc, 512, 0, 4096, 512, 512, 0);
    // 4) fcross kv on DEDUPED y (TS rows): y @ fcross_wqkv[:, 512:]  (1024 x 1024, K=512)
    gemm_kernel<<<dim3(16, 16), 256>>>(y, 512, 0, fcross_wqkv, 1536, 512, fcross_bqkv + 512,
                                       kv_fc, 1024, 0, 1024, 1024, 512, 0);
    // 9) pool MLP layer 1 (+tanh GELU): (1024 x 2048, K=4096)  [independent: issue early]
    gemm_kernel<<<dim3(32, 16), 256>>>(x_fast, 4096, 0, pool_w1, 2048, 0, pool_b1,
                                       h1, 2048, 0, 1024, POOLH, 4096, 1);
    // 5) fself attention (Tq=Tk=2048)
    attn_kernel<<<dim3(32, H_, B_), 256, SMEM_ATTN>>>(
        qkv_f, 1536, 0, qkv_f, 1536, 512, qkv_f, 1536, 1024,
        o1, 512, 0, LF_, LF_, scale);
    // 6) fcross attention (Tq=2048, Tk=512 — repeat folded out, exact)
    attn_kernel<<<dim3(32, H_, B_), 256, SMEM_ATTN>>>(
        q_fc, 512, 0, kv_fc, 1024, 0, kv_fc, 1024, 512,
        o2, 512, 0, LF_, TS_, scale);
    // 7) fself out-proj -> z_fast[:, :512]
    gemm_kernel<<<dim3(8, 64), 256>>>(o1, 512, 0, fself_wo, 512, 0, fself_bo,
                                      zf, 1024, 0, 4096, 512, 512, 0);
    // 8) fcross out-proj -> z_fast[:, 512:]
    gemm_kernel<<<dim3(8, 64), 256>>>(o2, 512, 0, fcross_wo, 512, 0, fcross_bo,
                                      zf, 1024, 512, 4096, 512, 512, 0);
    // 10) pool MLP layer 2: (1024 x 512, K=2048)
    gemm_kernel<<<dim3(8, 16), 256>>>(h1, 2048, 0, pool_w2, 512, 0, pool_b2,
                                      s, 512, 0, 1024, 512, 2048, 0);
    // 11) shift s by one slow step (zeros at t=0)
    shift_kernel<<<(B_ * TS_ * D2_ + 255) / 256, 256>>>(s, ss);
    // 12) sself qkv: s1 @ sself_wqkv                   (1024 x 1536, K=512)
    gemm_kernel<<<dim3(24, 16), 256>>>(x_slow, 1024, 0, sself_wqkv, 1536, 0, sself_bqkv,
                                       qkv_s, 1536, 0, 1024, 1536, 512, 0);
    // 13) scross q: s2 @ scross_wqkv[:, :512]
    gemm_kernel<<<dim3(8, 16), 256>>>(x_slow, 1024, 512, scross_wqkv, 1536, 0, scross_bqkv,
                                      q_sc, 512, 0, 1024, 512, 512, 0);
    // 14) scross kv: ss @ scross_wqkv[:, 512:]
    gemm_kernel<<<dim3(16, 16), 256>>>(ss, 512, 0, scross_wqkv, 1536, 512, scross_bqkv + 512,
                                       kv_sc, 1024, 0, 1024, 1024, 512, 0);
    // 15) sself attention (Tq=Tk=512)
    attn_kernel<<<dim3(8, H_, B_), 256, SMEM_ATTN>>>(
        qkv_s, 1536, 0, qkv_s, 1536, 512, qkv_s, 1536, 1024,
        o3, 512, 0, TS_, TS_, scale);
    // 16) scross attention (Tq=Tk=512)
    attn_kernel<<<dim3(8, H_, B_), 256, SMEM_ATTN>>>(
        q_sc, 512, 0, kv_sc, 1024, 0, kv_sc, 1024, 512,
        o4, 512, 0, TS_, TS_, scale);
    // 17) sself out-proj -> z_slow[:, :512]
    gemm_kernel<<<dim3(8, 16), 256>>>(o3, 512, 0, sself_wo, 512, 0, sself_bo,
                                      zs, 1024, 0, 1024, 512, 512, 0);
    // 18) scross out-proj -> z_slow[:, 512:]
    gemm_kernel<<<dim3(8, 16), 256>>>(o4, 512, 0, scross_wo, 512, 0, scross_bo,
                                      zs, 1024, 512, 1024, 512, 512, 0);
}

// round 3
// speedup vs baseline: 1.2287x; 1.2008x over previous
#include <cuda_runtime.h>
#include <cuda_bf16.h>
#include <math.h>

#define B_    2
#define LF_   2048
#define TS_   512
#define D2_   512
#define H_    8
#define HD_   64
#define POOLH 2048

typedef unsigned long long u64;
typedef unsigned int u32;

// ---------------------------------------------------------------------------
// Packed f32x2 helpers (attention kernel)
// ---------------------------------------------------------------------------
__device__ __forceinline__ u64 dup2(float x) {
    u64 r;
    asm("mov.b64 %0, {%1, %1};" : "=l"(r) : "f"(x));
    return r;
}
__device__ __forceinline__ u64 pack2(float x, float y) {
    u64 r;
    asm("mov.b64 %0, {%1, %2};" : "=l"(r) : "f"(x), "f"(y));
    return r;
}
__device__ __forceinline__ void unpack2(u64 v, float &x, float &y) {
    asm("mov.b64 {%0, %1}, %2;" : "=f"(x), "=f"(y) : "l"(v));
}
__device__ __forceinline__ void ffma2(u64 &acc, u64 a, u64 b) {
    asm("fma.rn.f32x2 %0, %1, %2, %0;" : "+l"(acc) : "l"(a), "l"(b));
}
__device__ __forceinline__ void fmul2(u64 &acc, u64 m) {
    asm("mul.rn.f32x2 %0, %0, %1;" : "+l"(acc) : "l"(m));
}

// ---------------------------------------------------------------------------
// bf16 split + pack helpers (tensor-core GEMM)
// ---------------------------------------------------------------------------
__device__ __forceinline__ void split_bf16(float x, float &hi, float &lo) {
    hi = __bfloat162float(__float2bfloat16(x));
    lo = x - hi;
}
__device__ __forceinline__ u32 pack_bf16(float a, float b) {
    __nv_bfloat162 t = __floats2bfloat162_rn(a, b);
    return *(u32*)&t;
}
__device__ __forceinline__ unsigned short bf16_bits(float a) {
    __nv_bfloat16 t = __float2bfloat16(a);
    return *(unsigned short*)&t;
}
__device__ __forceinline__ void mma_bf16(float c[4], u32 a0, u32 a1, u32 a2, u32 a3,
                                         u32 b0, u32 b1) {
    asm volatile(
        "mma.sync.aligned.m16n8k16.row.col.f32.bf16.bf16.f32 "
        "{%0,%1,%2,%3}, {%4,%5,%6,%7}, {%8,%9}, {%0,%1,%2,%3};\n"
        : "+f"(c[0]), "+f"(c[1]), "+f"(c[2]), "+f"(c[3])
        : "r"(a0), "r"(a1), "r"(a2), "r"(a3), "r"(b0), "r"(b1));
}

// ---------------------------------------------------------------------------
// Scratch
// ---------------------------------------------------------------------------
static const size_t O_Y     = 0;
static const size_t O_QKV_F = O_Y     + 524288;
static const size_t O_Q_FC  = O_QKV_F + 6291456;
static const size_t O_KV_FC = O_Q_FC  + 2097152;
static const size_t O_O1    = O_KV_FC + 1048576;
static const size_t O_O2    = O_O1    + 2097152;
static const size_t O_H1    = O_O2    + 2097152;
static const size_t O_S     = O_H1    + 2097152;
static const size_t O_SS    = O_S     + 524288;
static const size_t O_QKV_S = O_SS    + 524288;
static const size_t O_Q_SC  = O_QKV_S + 1572864;
static const size_t O_KV_SC = O_Q_SC  + 524288;
static const size_t O_O3    = O_KV_SC + 1048576;
static const size_t O_O4    = O_O3    + 524288;
static const size_t SCRATCH_FLOATS = O_O4 + 524288;

__device__ float g_scratch[SCRATCH_FLOATS];

// ---------------------------------------------------------------------------
// Tensor-core SGEMM via split-bf16 (hi/lo), fp32 accumulate.
// C[m, coff+n] = act( A[m, aoff+k] * W[k, woff+n] + bias[n] )
// Block tile 128x64, K-chunk 32, 256 threads (8 warps, 4x2), warp tile 32x32.
// Requires M%128==0, N%64==0, K%32==0.
// ---------------------------------------------------------------------------
#define AS_STRIDE 40   // ushort stride per row (k dim), conflict-free for frag loads
#define WS_STRIDE 40

__global__ __launch_bounds__(256) void gemm_bf16_kernel(
    const float* __restrict__ A, int lda, int aoff,
    const float* __restrict__ W, int ldw, int woff,
    const float* __restrict__ bias,
    float* __restrict__ C, int ldc, int coff,
    int M, int N, int K, int act)
{
    __shared__ __align__(16) unsigned short As[2 * 128 * AS_STRIDE]; // [s][m][k]
    __shared__ __align__(16) unsigned short Ws[2 * 64 * WS_STRIDE];  // [s][n][k]

    const int tid  = threadIdx.x;
    const int lane = tid & 31;
    const int warp = tid >> 5;
    const int warp_m = warp >> 1;       // 0..3
    const int warp_n = warp & 1;        // 0..1
    const int g  = lane >> 2;           // group id 0..7
    const int tg = lane & 3;            // thread in group 0..3

    const int m0 = blockIdx.y * 128, n0 = blockIdx.x * 64;

    float acc[2][4][4];                 // [mt][nt][reg]
    #pragma unroll
    for (int mt = 0; mt < 2; mt++)
        #pragma unroll
        for (int nt = 0; nt < 4; nt++)
            #pragma unroll
            for (int r = 0; r < 4; r++) acc[mt][nt][r] = 0.f;

    // gmem load coords
    const int a_row = tid >> 3;             // 0..31 (rows, stepped by 32 over 4 passes)
    const int a_kc  = (tid & 7) * 4;        // 0..28
    const int w_k   = tid >> 4;             // 0..15 (k, stepped by 16 over 2 passes)
    const int w_n4  = (tid & 15) * 4;       // 0..60

    for (int k0 = 0; k0 < K; k0 += 32) {
        // prefetch gmem into regs
        float4 av[4], wv[2];
        #pragma unroll
        for (int p = 0; p < 4; p++)
            av[p] = *(const float4*)(A + (size_t)(m0 + a_row + 32 * p) * lda + aoff + k0 + a_kc);
        #pragma unroll
        for (int p = 0; p < 2; p++)
            wv[p] = *(const float4*)(W + (size_t)(k0 + w_k + 16 * p) * ldw + woff + n0 + w_n4);

        __syncthreads();

        // store A tile: hi/lo, [m][k], packed 2 bf16 per 32-bit word
        #pragma unroll
        for (int p = 0; p < 4; p++) {
            const int m = a_row + 32 * p;
            float hx, lx, hy, ly, hz, lz, hw, lw;
            split_bf16(av[p].x, hx, lx); split_bf16(av[p].y, hy, ly);
            split_bf16(av[p].z, hz, lz); split_bf16(av[p].w, hw, lw);
            unsigned short* rh = &As[(size_t)m * AS_STRIDE + a_kc];
            unsigned short* rl = &As[(size_t)(128 + m) * AS_STRIDE + a_kc];
            *(u32*)&rh[0] = pack_bf16(hx, hy);
            *(u32*)&rh[2] = pack_bf16(hz, hw);
            *(u32*)&rl[0] = pack_bf16(lx, ly);
            *(u32*)&rl[2] = pack_bf16(lz, lw);
        }
        // store W tile transposed: [n][k]
        #pragma unroll
        for (int p = 0; p < 2; p++) {
            const int k = w_k + 16 * p;
            const float vals[4] = {wv[p].x, wv[p].y, wv[p].z, wv[p].w};
            #pragma unroll
            for (int j = 0; j < 4; j++) {
                float hi, lo;
                split_bf16(vals[j], hi, lo);
                Ws[(size_t)(w_n4 + j) * WS_STRIDE + k]        = bf16_bits(hi);
                Ws[(size_t)(64 + w_n4 + j) * WS_STRIDE + k]   = bf16_bits(lo);
            }
        }
        __syncthreads();

        // MMA over two k16 chunks (word offsets 0 and 8)
        #pragma unroll
        for (int kk = 0; kk < 2; kk++) {
            const int kw = kk * 8 + tg;   // word index (k = 2*kw)
            u32 afr[2][2][4];             // [s][mt][reg]
            #pragma unroll
            for (int s = 0; s < 2; s++)
                #pragma unroll
                for (int mt = 0; mt < 2; mt++) {
                    const int m = warp_m * 32 + mt * 16 + g;
                    const unsigned short* r0 = &As[(size_t)(s * 128 + m) * AS_STRIDE];
                    const unsigned short* r1 = &As[(size_t)(s * 128 + m + 8) * AS_STRIDE];
                    afr[s][mt][0] = *(const u32*)&r0[2 * kw];
                    afr[s][mt][1] = *(const u32*)&r1[2 * kw];
                    afr[s][mt][2] = *(const u32*)&r0[2 * (kw + 4)];
                    afr[s][mt][3] = *(const u32*)&r1[2 * (kw + 4)];
                }
            u32 bfr[2][4][2];             // [s][nt][reg]
            #pragma unroll
            for (int s = 0; s < 2; s++)
                #pragma unroll
                for (int nt = 0; nt < 4; nt++) {
                    const int n = warp_n * 32 + nt * 8 + g;
                    const unsigned short* r = &Ws[(size_t)(s * 64 + n) * WS_STRIDE];
                    bfr[s][nt][0] = *(const u32*)&r[2 * kw];
                    bfr[s][nt][1] = *(const u32*)&r[2 * (kw + 4)];
                }
            #pragma unroll
            for (int mt = 0; mt < 2; mt++)
                #pragma unroll
                for (int nt = 0; nt < 4; nt++) {
                    // hi*hi + hi*lo + lo*hi
                    mma_bf16(acc[mt][nt], afr[0][mt][0], afr[0][mt][1], afr[0][mt][2], afr[0][mt][3],
                             bfr[0][nt][0], bfr[0][nt][1]);
                    mma_bf16(acc[mt][nt], afr[0][mt][0], afr[0][mt][1], afr[0][mt][2], afr[0][mt][3],
                             bfr[1][nt][0], bfr[1][nt][1]);
                    mma_bf16(acc[mt][nt], afr[1][mt][0], afr[1][mt][1], afr[1][mt][2], afr[1][mt][3],
                             bfr[0][nt][0], bfr[0][nt][1]);
                }
        }
    }

    // epilogue
    #pragma unroll
    for (int mt = 0; mt < 2; mt++) {
        #pragma unroll
        for (int nt = 0; nt < 4; nt++) {
            const int m = m0 + warp_m * 32 + mt * 16 + g;
            const int n = n0 + warp_n * 32 + nt * 8 + tg * 2;
            const float bb0 = bias[n], bb1 = bias[n + 1];
            float v[4] = {acc[mt][nt][0] + bb0, acc[mt][nt][1] + bb1,
                          acc[mt][nt][2] + bb0, acc[mt][nt][3] + bb1};
            if (act == 1) {
                #pragma unroll
                for (int r = 0; r < 4; r++) {
                    float x = v[r];
                    float u = 0.7978845608028654f * (x + 0.044715f * x * x * x);
                    v[r] = 0.5f * x * (1.0f + tanhf(u));
                }
            }
            *(float2*)(C + (size_t)m * ldc + coff + n)       = make_float2(v[0], v[1]);
            *(float2*)(C + (size_t)(m + 8) * ldc + coff + n) = make_float2(v[2], v[3]);
        }
    }
}

// ---------------------------------------------------------------------------
// Flash attention (fp32, online softmax, FFMA2 inner loops). hd=64.
// ---------------------------------------------------------------------------
#define SMEM_ATTN (4 * 64 * 68 * 4)

__global__ __launch_bounds__(256) void attn_kernel(
    const float* __restrict__ Q, int ldq, int qoff,
    const float* __restrict__ Kp, int ldk, int koff,
    const float* __restrict__ Vp, int ldv, int voff,
    float* __restrict__ O, int ldo, int ooff,
    int Tq, int Tk, float scale)
{
    extern __shared__ float sm[];
    float (*QsT)[68] = (float(*)[68])(sm);
    float (*KsT)[68] = (float(*)[68])(sm + 64 * 68);
    float (*Vs )[68] = (float(*)[68])(sm + 2 * 64 * 68);
    float (*PsT)[68] = (float(*)[68])(sm + 3 * 64 * 68);

    const int tid = threadIdx.x;
    const int ty = tid >> 4, tx = tid & 15;
    const int b = blockIdx.z, h = blockIdx.y, qt = blockIdx.x;

    const float* Qb = Q  + (size_t)(b * Tq + qt * 64) * ldq + qoff + h * HD_;
    const float* Kb = Kp + (size_t)(b * Tk) * ldk + koff + h * HD_;
    const float* Vb = Vp + (size_t)(b * Tk) * ldv + voff + h * HD_;

    for (int e = tid; e < 64 * 16; e += 256) {
        const int r = e >> 4, c4 = e & 15;
        float4 q4 = *(const float4*)(Qb + (size_t)r * ldq + c4 * 4);
        QsT[c4 * 4 + 0][r] = q4.x * scale;
        QsT[c4 * 4 + 1][r] = q4.y * scale;
        QsT[c4 * 4 + 2][r] = q4.z * scale;
        QsT[c4 * 4 + 3][r] = q4.w * scale;
    }

    float m_i[4], l_i[4];
    u64 acc2[2][4];
    #pragma unroll
    for (int i = 0; i < 4; i++) { m_i[i] = -1e30f; l_i[i] = 0.f; }
    #pragma unroll
    for (int p = 0; p < 2; p++)
        #pragma unroll
        for (int j = 0; j < 4; j++) acc2[p][j] = 0ull;

    for (int kt = 0; kt < Tk; kt += 64) {
        __syncthreads();
        for (int e = tid; e < 64 * 16; e += 256) {
            const int r = e >> 4, c4 = e & 15;
            float4 k4 = *(const float4*)(Kb + (size_t)(kt + r) * ldk + c4 * 4);
            KsT[c4 * 4 + 0][r] = k4.x;
            KsT[c4 * 4 + 1][r] = k4.y;
            KsT[c4 * 4 + 2][r] = k4.z;
            KsT[c4 * 4 + 3][r] = k4.w;
            float4 v4 = *(const float4*)(Vb + (size_t)(kt + r) * ldv + c4 * 4);
            *(float4*)&Vs[r][c4 * 4] = v4;
        }
        __syncthreads();

        u64 s2[2][4] = {};
        #pragma unroll
        for (int kk = 0; kk < 64; kk++) {
            u64 q01 = *(const u64*)&QsT[kk][ty * 4];
            u64 q23 = *(const u64*)&QsT[kk][ty * 4 + 2];
            float4 kv = *(const float4*)&KsT[kk][tx * 4];
            u64 b0 = dup2(kv.x), b1 = dup2(kv.y), b2 = dup2(kv.z), b3 = dup2(kv.w);
            ffma2(s2[0][0], q01, b0);
            ffma2(s2[0][1], q01, b1);
            ffma2(s2[0][2], q01, b2);
            ffma2(s2[0][3], q01, b3);
            ffma2(s2[1][0], q23, b0);
            ffma2(s2[1][1], q23, b1);
            ffma2(s2[1][2], q23, b2);
            ffma2(s2[1][3], q23, b3);
        }
        float s[4][4];
        #pragma unroll
        for (int p = 0; p < 2; p++)
            #pragma unroll
            for (int j = 0; j < 4; j++) unpack2(s2[p][j], s[2 * p][j], s[2 * p + 1][j]);

        float corr[4];
        #pragma unroll
        for (int i = 0; i < 4; i++) {
            float rm = fmaxf(fmaxf(s[i][0], s[i][1]), fmaxf(s[i][2], s[i][3]));
            #pragma unroll
            for (int off = 8; off > 0; off >>= 1)
                rm = fmaxf(rm, __shfl_xor_sync(0xffffffffu, rm, off));
            const float mn = fmaxf(m_i[i], rm);
            corr[i] = __expf(m_i[i] - mn);
            float rs = 0.f;
            #pragma unroll
            for (int j = 0; j < 4; j++) {
                float p = __expf(s[i][j] - mn);
                s[i][j] = p;
                rs += p;
            }
            #pragma unroll
            for (int off = 8; off > 0; off >>= 1)
                rs += __shfl_xor_sync(0xffffffffu, rs, off);
            l_i[i] = l_i[i] * corr[i] + rs;
            m_i[i] = mn;
            #pragma unroll
            for (int j = 0; j < 4; j++) PsT[tx * 4 + j][ty * 4 + i] = s[i][j];
        }
        #pragma unroll
        for (int p = 0; p < 2; p++) {
            u64 c = pack2(corr[2 * p], corr[2 * p + 1]);
            #pragma unroll
            for (int j = 0; j < 4; j++) fmul2(acc2[p][j], c);
        }
        __syncthreads();

        #pragma unroll
        for (int jj = 0; jj < 64; jj++) {
            u64 p01 = *(const u64*)&PsT[jj][ty * 4];
            u64 p23 = *(const u64*)&PsT[jj][ty * 4 + 2];
            float4 vv = *(const float4*)&Vs[jj][tx * 4];
            u64 b0 = dup2(vv.x), b1 = dup2(vv.y), b2 = dup2(vv.z), b3 = dup2(vv.w);
            ffma2(acc2[0][0], p01, b0);
            ffma2(acc2[0][1], p01, b1);
            ffma2(acc2[0][2], p01, b2);
            ffma2(acc2[0][3], p01, b3);
            ffma2(acc2[1][0], p23, b0);
            ffma2(acc2[1][1], p23, b1);
            ffma2(acc2[1][2], p23, b2);
            ffma2(acc2[1][3], p23, b3);
        }
    }

    float* Ob = O + (size_t)(b * Tq + qt * 64) * ldo + ooff + h * HD_;
    #pragma unroll
    for (int p = 0; p < 2; p++) {
        float r0[4], r1[4];
        #pragma unroll
        for (int j = 0; j < 4; j++) unpack2(acc2[p][j], r0[j], r1[j]);
        const float inv0 = 1.0f / l_i[2 * p];
        const float inv1 = 1.0f / l_i[2 * p + 1];
        *(float4*)(Ob + (size_t)(ty * 4 + 2 * p) * ldo + tx * 4) =
            make_float4(r0[0] * inv0, r0[1] * inv0, r0[2] * inv0, r0[3] * inv0);
        *(float4*)(Ob + (size_t)(ty * 4 + 2 * p + 1) * ldo + tx * 4) =
            make_float4(r1[0] * inv1, r1[1] * inv1, r1[2] * inv1, r1[3] * inv1);
    }
}

// ---------------------------------------------------------------------------
// Shifted copy for slow path
// ---------------------------------------------------------------------------
__global__ void shift_kernel(const float* __restrict__ src, float* __restrict__ dst)
{
    const int e = blockIdx.x * 256 + threadIdx.x;
    if (e >= B_ * TS_ * D2_) return;
    const int t = (e / D2_) % TS_;
    dst[e] = (t == 0) ? 0.f : src[e - D2_];
}

// ---------------------------------------------------------------------------
// Host orchestration
// ---------------------------------------------------------------------------
extern "C" void kernel_launch(void* const* d_in, const int* in_sizes, int n_in,
                              void* d_out, int out_size)
{
    (void)in_sizes; (void)n_in; (void)out_size;

    const float* x_fast      = (const float*)d_in[0];
    const float* x_slow      = (const float*)d_in[1];
    const float* fself_wqkv  = (const float*)d_in[2];
    const float* fself_bqkv  = (const float*)d_in[3];
    const float* fself_wo    = (const float*)d_in[4];
    const float* fself_bo    = (const float*)d_in[5];
    const float* fcross_wqkv = (const float*)d_in[6];
    const float* fcross_bqkv = (const float*)d_in[7];
    const float* fcross_wo   = (const float*)d_in[8];
    const float* fcross_bo   = (const float*)d_in[9];
    const float* sself_wqkv  = (const float*)d_in[10];
    const float* sself_bqkv  = (const float*)d_in[11];
    const float* sself_wo    = (const float*)d_in[12];
    const float* sself_bo    = (const float*)d_in[13];
    const float* scross_wqkv = (const float*)d_in[14];
    const float* scross_bqkv = (const float*)d_in[15];
    const float* scross_wo   = (const float*)d_in[16];
    const float* scross_bo   = (const float*)d_in[17];
    const float* lift_w      = (const float*)d_in[18];
    const float* lift_b      = (const float*)d_in[19];
    const float* pool_w1     = (const float*)d_in[20];
    const float* pool_b1     = (const float*)d_in[21];
    const float* pool_w2     = (const float*)d_in[22];
    const float* pool_b2     = (const float*)d_in[23];

    float* out = (float*)d_out;
    float* zf = out;
    float* zs = out + (size_t)B_ * LF_ * 1024;

    float* S0 = nullptr;
    cudaGetSymbolAddress((void**)&S0, g_scratch);
    float* y     = S0 + O_Y;
    float* qkv_f = S0 + O_QKV_F;
    float* q_fc  = S0 + O_Q_FC;
    float* kv_fc = S0 + O_KV_FC;
    float* o1    = S0 + O_O1;
    float* o2    = S0 + O_O2;
    float* h1    = S0 + O_H1;
    float* s     = S0 + O_S;
    float* ss    = S0 + O_SS;
    float* qkv_s = S0 + O_QKV_S;
    float* q_sc  = S0 + O_Q_SC;
    float* kv_sc = S0 + O_KV_SC;
    float* o3    = S0 + O_O3;
    float* o4    = S0 + O_O4;

    cudaFuncSetAttribute(attn_kernel,
                         cudaFuncAttributeMaxDynamicSharedMemorySize, SMEM_ATTN);

    const float scale = 0.125f;  // 1/sqrt(64)

    // 1) lift: (1024 x 512, K=1024)
    gemm_bf16_kernel<<<dim3(8, 8), 256>>>(x_slow, 1024, 0, lift_w, 512, 0, lift_b,
                                          y, 512, 0, 1024, 512, 1024, 0);
    // 2) fself qkv: (4096 x 1536, K=512)
    gemm_bf16_kernel<<<dim3(24, 32), 256>>>(x_fast, 1024, 0, fself_wqkv, 1536, 0, fself_bqkv,
                                            qkv_f, 1536, 0, 4096, 1536, 512, 0);
    // 3) fcross q: (4096 x 512, K=512)
    gemm_bf16_kernel<<<dim3(8, 32), 256>>>(x_fast, 1024, 512, fcross_wqkv, 1536, 0, fcross_bqkv,
                                           q_fc, 512, 0, 4096, 512, 512, 0);
    // 4) fcross kv on deduped y: (1024 x 1024, K=512)
    gemm_bf16_kernel<<<dim3(16, 8), 256>>>(y, 512, 0, fcross_wqkv, 1536, 512, fcross_bqkv + 512,
                                           kv_fc, 1024, 0, 1024, 1024, 512, 0);
    // 9) pool MLP layer 1 (+GELU): (1024 x 2048, K=4096)
    gemm_bf16_kernel<<<dim3(32, 8), 256>>>(x_fast, 4096, 0, pool_w1, 2048, 0, pool_b1,
                                           h1, 2048, 0, 1024, POOLH, 4096, 1);
    // 5) fself attention (Tq=Tk=2048)
    attn_kernel<<<dim3(32, H_, B_), 256, SMEM_ATTN>>>(
        qkv_f, 1536, 0, qkv_f, 1536, 512, qkv_f, 1536, 1024,
        o1, 512, 0, LF_, LF_, scale);
    // 6) fcross attention (Tq=2048, Tk=512)
    attn_kernel<<<dim3(32, H_, B_), 256, SMEM_ATTN>>>(
        q_fc, 512, 0, kv_fc, 1024, 0, kv_fc, 1024, 512,
        o2, 512, 0, LF_, TS_, scale);
    // 7) fself out-proj
    gemm_bf16_kernel<<<dim3(8, 32), 256>>>(o1, 512, 0, fself_wo, 512, 0, fself_bo,
                                           zf, 1024, 0, 4096, 512, 512, 0);
    // 8) fcross out-proj
    gemm_bf16_kernel<<<dim3(8, 32), 256>>>(o2, 512, 0, fcross_wo, 512, 0, fcross_bo,
                                           zf, 1024, 512, 4096, 512, 512, 0);
    // 10) pool MLP layer 2: (1024 x 512, K=2048)
    gemm_bf16_kernel<<<dim3(8, 8), 256>>>(h1, 2048, 0, pool_w2, 512, 0, pool_b2,
                                          s, 512, 0, 1024, 512, 2048, 0);
    // 11) shift
    shift_kernel<<<(B_ * TS_ * D2_ + 255) / 256, 256>>>(s, ss);
    // 12) sself qkv: (1024 x 1536, K=512)
    gemm_bf16_kernel<<<dim3(24, 8), 256>>>(x_slow, 1024, 0, sself_wqkv, 1536, 0, sself_bqkv,
                                           qkv_s, 1536, 0, 1024, 1536, 512, 0);
    // 13) scross q
    gemm_bf16_kernel<<<dim3(8, 8), 256>>>(x_slow, 1024, 512, scross_wqkv, 1536, 0, scross_bqkv,
                                          q_sc, 512, 0, 1024, 512, 512, 0);
    // 14) scross kv
    gemm_bf16_kernel<<<dim3(16, 8), 256>>>(ss, 512, 0, scross_wqkv, 1536, 512, scross_bqkv + 512,
                                           kv_sc, 1024, 0, 1024, 1024, 512, 0);
    // 15) sself attention
    attn_kernel<<<dim3(8, H_, B_), 256, SMEM_ATTN>>>(
        qkv_s, 1536, 0, qkv_s, 1536, 512, qkv_s, 1536, 1024,
        o3, 512, 0, TS_, TS_, scale);
    // 16) scross attention
    attn_kernel<<<dim3(8, H_, B_), 256, SMEM_ATTN>>>(
        q_sc, 512, 0, kv_sc, 1024, 0, kv_sc, 1024, 512,
        o4, 512, 0, TS_, TS_, scale);
    // 17) sself out-proj
    gemm_bf16_kernel<<<dim3(8, 8), 256>>>(o3, 512, 0, sself_wo, 512, 0, sself_bo,
                                          zs, 1024, 0, 1024, 512, 512, 0);
    // 18) scross out-proj
    gemm_bf16_kernel<<<dim3(8, 8), 256>>>(o4, 512, 0, scross_wo, 512, 0, scross_bo,
                                          zs, 1024, 512, 1024, 512, 512, 0);
}

// round 4
// speedup vs baseline: 1.5990x; 1.3014x over previous
#include <cuda_runtime.h>
#include <cuda_bf16.h>
#include <math.h>

#define B_    2
#define LF_   2048
#define TS_   512
#define D2_   512
#define H_    8
#define HD_   64
#define POOLH 2048

typedef unsigned long long u64;
typedef unsigned int u32;
typedef unsigned short u16;

// ---------------------------------------------------------------------------
// bf16 split + pack helpers
// ---------------------------------------------------------------------------
__device__ __forceinline__ void split_bf16(float x, float &hi, float &lo) {
    hi = __bfloat162float(__float2bfloat16(x));
    lo = x - hi;
}
__device__ __forceinline__ u32 pack_bf16(float a, float b) {
    __nv_bfloat162 t = __floats2bfloat162_rn(a, b);
    return *(u32*)&t;
}
__device__ __forceinline__ u16 bf16_bits(float a) {
    __nv_bfloat16 t = __float2bfloat16(a);
    return *(u16*)&t;
}
__device__ __forceinline__ void mma_bf16(float c[4], u32 a0, u32 a1, u32 a2, u32 a3,
                                         u32 b0, u32 b1) {
    asm volatile(
        "mma.sync.aligned.m16n8k16.row.col.f32.bf16.bf16.f32 "
        "{%0,%1,%2,%3}, {%4,%5,%6,%7}, {%8,%9}, {%0,%1,%2,%3};\n"
        : "+f"(c[0]), "+f"(c[1]), "+f"(c[2]), "+f"(c[3])
        : "r"(a0), "r"(a1), "r"(a2), "r"(a3), "r"(b0), "r"(b1));
}

// ---------------------------------------------------------------------------
// Scratch
// ---------------------------------------------------------------------------
static const size_t O_Y     = 0;
static const size_t O_QKV_F = O_Y     + 524288;
static const size_t O_Q_FC  = O_QKV_F + 6291456;
static const size_t O_KV_FC = O_Q_FC  + 2097152;
static const size_t O_O1    = O_KV_FC + 1048576;
static const size_t O_O2    = O_O1    + 2097152;
static const size_t O_H1    = O_O2    + 2097152;
static const size_t O_S     = O_H1    + 2097152;
static const size_t O_SS    = O_S     + 524288;
static const size_t O_QKV_S = O_SS    + 524288;
static const size_t O_Q_SC  = O_QKV_S + 1572864;
static const size_t O_KV_SC = O_Q_SC  + 524288;
static const size_t O_O3    = O_KV_SC + 1048576;
static const size_t O_O4    = O_O3    + 524288;
static const size_t SCRATCH_FLOATS = O_O4 + 524288;

__device__ float g_scratch[SCRATCH_FLOATS];

// ---------------------------------------------------------------------------
// Tensor-core SGEMM via split-bf16 (hi/lo), fp32 accumulate. (unchanged, verified)
// ---------------------------------------------------------------------------
#define AS_STRIDE 40
#define WS_STRIDE 40

__global__ __launch_bounds__(256) void gemm_bf16_kernel(
    const float* __restrict__ A, int lda, int aoff,
    const float* __restrict__ W, int ldw, int woff,
    const float* __restrict__ bias,
    float* __restrict__ C, int ldc, int coff,
    int M, int N, int K, int act)
{
    __shared__ __align__(16) u16 As[2 * 128 * AS_STRIDE];
    __shared__ __align__(16) u16 Ws[2 * 64 * WS_STRIDE];

    const int tid  = threadIdx.x;
    const int lane = tid & 31;
    const int warp = tid >> 5;
    const int warp_m = warp >> 1;
    const int warp_n = warp & 1;
    const int g  = lane >> 2;
    const int tg = lane & 3;

    const int m0 = blockIdx.y * 128, n0 = blockIdx.x * 64;

    float acc[2][4][4];
    #pragma unroll
    for (int mt = 0; mt < 2; mt++)
        #pragma unroll
        for (int nt = 0; nt < 4; nt++)
            #pragma unroll
            for (int r = 0; r < 4; r++) acc[mt][nt][r] = 0.f;

    const int a_row = tid >> 3;
    const int a_kc  = (tid & 7) * 4;
    const int w_k   = tid >> 4;
    const int w_n4  = (tid & 15) * 4;

    for (int k0 = 0; k0 < K; k0 += 32) {
        float4 av[4], wv[2];
        #pragma unroll
        for (int p = 0; p < 4; p++)
            av[p] = *(const float4*)(A + (size_t)(m0 + a_row + 32 * p) * lda + aoff + k0 + a_kc);
        #pragma unroll
        for (int p = 0; p < 2; p++)
            wv[p] = *(const float4*)(W + (size_t)(k0 + w_k + 16 * p) * ldw + woff + n0 + w_n4);

        __syncthreads();

        #pragma unroll
        for (int p = 0; p < 4; p++) {
            const int m = a_row + 32 * p;
            float hx, lx, hy, ly, hz, lz, hw, lw;
            split_bf16(av[p].x, hx, lx); split_bf16(av[p].y, hy, ly);
            split_bf16(av[p].z, hz, lz); split_bf16(av[p].w, hw, lw);
            u16* rh = &As[(size_t)m * AS_STRIDE + a_kc];
            u16* rl = &As[(size_t)(128 + m) * AS_STRIDE + a_kc];
            *(u32*)&rh[0] = pack_bf16(hx, hy);
            *(u32*)&rh[2] = pack_bf16(hz, hw);
            *(u32*)&rl[0] = pack_bf16(lx, ly);
            *(u32*)&rl[2] = pack_bf16(lz, lw);
        }
        #pragma unroll
        for (int p = 0; p < 2; p++) {
            const int k = w_k + 16 * p;
            const float vals[4] = {wv[p].x, wv[p].y, wv[p].z, wv[p].w};
            #pragma unroll
            for (int j = 0; j < 4; j++) {
                float hi, lo;
                split_bf16(vals[j], hi, lo);
                Ws[(size_t)(w_n4 + j) * WS_STRIDE + k]      = bf16_bits(hi);
                Ws[(size_t)(64 + w_n4 + j) * WS_STRIDE + k] = bf16_bits(lo);
            }
        }
        __syncthreads();

        #pragma unroll
        for (int kk = 0; kk < 2; kk++) {
            const int kw = kk * 8 + tg;
            u32 afr[2][2][4];
            #pragma unroll
            for (int s = 0; s < 2; s++)
                #pragma unroll
                for (int mt = 0; mt < 2; mt++) {
                    const int m = warp_m * 32 + mt * 16 + g;
                    const u16* r0 = &As[(size_t)(s * 128 + m) * AS_STRIDE];
                    const u16* r1 = &As[(size_t)(s * 128 + m + 8) * AS_STRIDE];
                    afr[s][mt][0] = *(const u32*)&r0[2 * kw];
                    afr[s][mt][1] = *(const u32*)&r1[2 * kw];
                    afr[s][mt][2] = *(const u32*)&r0[2 * (kw + 4)];
                    afr[s][mt][3] = *(const u32*)&r1[2 * (kw + 4)];
                }
            u32 bfr[2][4][2];
            #pragma unroll
            for (int s = 0; s < 2; s++)
                #pragma unroll
                for (int nt = 0; nt < 4; nt++) {
                    const int n = warp_n * 32 + nt * 8 + g;
                    const u16* r = &Ws[(size_t)(s * 64 + n) * WS_STRIDE];
                    bfr[s][nt][0] = *(const u32*)&r[2 * kw];
                    bfr[s][nt][1] = *(const u32*)&r[2 * (kw + 4)];
                }
            #pragma unroll
            for (int mt = 0; mt < 2; mt++)
                #pragma unroll
                for (int nt = 0; nt < 4; nt++) {
                    mma_bf16(acc[mt][nt], afr[0][mt][0], afr[0][mt][1], afr[0][mt][2], afr[0][mt][3],
                             bfr[0][nt][0], bfr[0][nt][1]);
                    mma_bf16(acc[mt][nt], afr[0][mt][0], afr[0][mt][1], afr[0][mt][2], afr[0][mt][3],
                             bfr[1][nt][0], bfr[1][nt][1]);
                    mma_bf16(acc[mt][nt], afr[1][mt][0], afr[1][mt][1], afr[1][mt][2], afr[1][mt][3],
                             bfr[0][nt][0], bfr[0][nt][1]);
                }
        }
    }

    #pragma unroll
    for (int mt = 0; mt < 2; mt++) {
        #pragma unroll
        for (int nt = 0; nt < 4; nt++) {
            const int m = m0 + warp_m * 32 + mt * 16 + g;
            const int n = n0 + warp_n * 32 + nt * 8 + tg * 2;
            const float bb0 = bias[n], bb1 = bias[n + 1];
            float v[4] = {acc[mt][nt][0] + bb0, acc[mt][nt][1] + bb1,
                          acc[mt][nt][2] + bb0, acc[mt][nt][3] + bb1};
            if (act == 1) {
                #pragma unroll
                for (int r = 0; r < 4; r++) {
                    float x = v[r];
                    float u = 0.7978845608028654f * (x + 0.044715f * x * x * x);
                    v[r] = 0.5f * x * (1.0f + tanhf(u));
                }
            }
            *(float2*)(C + (size_t)m * ldc + coff + n)       = make_float2(v[0], v[1]);
            *(float2*)(C + (size_t)(m + 8) * ldc + coff + n) = make_float2(v[2], v[3]);
        }
    }
}

// ---------------------------------------------------------------------------
// Flash attention on tensor cores (split-bf16 hi/lo, fp32 softmax & accum).
// 64 q-rows/CTA, 4 warps (m16 strip each), 64-key tiles, P kept in registers.
// Grid: (Tq/64, H, B), 128 threads.
// ---------------------------------------------------------------------------
#define AT_STRIDE 72   // ushorts per row; 36 words -> conflict-free frag loads
#define SMEM_ATTN_MMA (3 * 128 * AT_STRIDE * 2)   // Q,K,V hi/lo tiles (55296 B)

__global__ __launch_bounds__(128) void attn_mma_kernel(
    const float* __restrict__ Q, int ldq, int qoff,
    const float* __restrict__ Kp, int ldk, int koff,
    const float* __restrict__ Vp, int ldv, int voff,
    float* __restrict__ O, int ldo, int ooff,
    int Tq, int Tk, float scale)
{
    extern __shared__ __align__(16) u16 smu[];
    u16 (*Qs)[AT_STRIDE] = (u16(*)[AT_STRIDE])smu;         // rows 0-63 hi, 64-127 lo  [row][dim]
    u16 (*Ks)[AT_STRIDE] = Qs + 128;                        // [key][dim] hi/lo
    u16 (*Vs)[AT_STRIDE] = Ks + 128;                        // [dim][key] hi/lo (transposed)

    const int tid  = threadIdx.x;
    const int lane = tid & 31;
    const int warp = tid >> 5;
    const int g  = lane >> 2;
    const int tg = lane & 3;
    const int mrow = warp * 16;

    const int b = blockIdx.z, h = blockIdx.y, qt = blockIdx.x;
    const float* Qb = Q  + (size_t)(b * Tq + qt * 64) * ldq + qoff + h * HD_;
    const float* Kb = Kp + (size_t)(b * Tk) * ldk + koff + h * HD_;
    const float* Vb = Vp + (size_t)(b * Tk) * ldv + voff + h * HD_;

    // load Q tile (scaled) -> hi/lo bf16 smem
    for (int e = tid; e < 64 * 16; e += 128) {
        const int r = e >> 4, c = (e & 15) * 4;
        float4 q4 = *(const float4*)(Qb + (size_t)r * ldq + c);
        float h0, l0, h1, l1, h2, l2, h3, l3;
        split_bf16(q4.x * scale, h0, l0); split_bf16(q4.y * scale, h1, l1);
        split_bf16(q4.z * scale, h2, l2); split_bf16(q4.w * scale, h3, l3);
        *(u32*)&Qs[r][c]          = pack_bf16(h0, h1);
        *(u32*)&Qs[r][c + 2]      = pack_bf16(h2, h3);
        *(u32*)&Qs[64 + r][c]     = pack_bf16(l0, l1);
        *(u32*)&Qs[64 + r][c + 2] = pack_bf16(l2, l3);
    }

    float acc[8][4];
    #pragma unroll
    for (int nt = 0; nt < 8; nt++)
        #pragma unroll
        for (int r = 0; r < 4; r++) acc[nt][r] = 0.f;
    float mx0 = -1e30f, mx1 = -1e30f, lsum0 = 0.f, lsum1 = 0.f;

    for (int kt = 0; kt < Tk; kt += 64) {
        __syncthreads();
        for (int e = tid; e < 64 * 16; e += 128) {
            const int r = e >> 4, c = (e & 15) * 4;
            float4 k4 = *(const float4*)(Kb + (size_t)(kt + r) * ldk + c);
            float h0, l0, h1, l1, h2, l2, h3, l3;
            split_bf16(k4.x, h0, l0); split_bf16(k4.y, h1, l1);
            split_bf16(k4.z, h2, l2); split_bf16(k4.w, h3, l3);
            *(u32*)&Ks[r][c]          = pack_bf16(h0, h1);
            *(u32*)&Ks[r][c + 2]      = pack_bf16(h2, h3);
            *(u32*)&Ks[64 + r][c]     = pack_bf16(l0, l1);
            *(u32*)&Ks[64 + r][c + 2] = pack_bf16(l2, l3);
            float4 v4 = *(const float4*)(Vb + (size_t)(kt + r) * ldv + c);
            float vh[4], vl[4];
            split_bf16(v4.x, vh[0], vl[0]); split_bf16(v4.y, vh[1], vl[1]);
            split_bf16(v4.z, vh[2], vl[2]); split_bf16(v4.w, vh[3], vl[3]);
            #pragma unroll
            for (int i = 0; i < 4; i++) {
                Vs[c + i][r]      = bf16_bits(vh[i]);
                Vs[64 + c + i][r] = bf16_bits(vl[i]);
            }
        }
        __syncthreads();

        // ---- S = Q K^T (hi*hi + hi*lo + lo*hi) ----
        float s[8][4];
        #pragma unroll
        for (int nt = 0; nt < 8; nt++)
            #pragma unroll
            for (int r = 0; r < 4; r++) s[nt][r] = 0.f;

        #pragma unroll
        for (int kc = 0; kc < 4; kc++) {
            const int w = kc * 8 + tg;
            u32 a[2][4];
            #pragma unroll
            for (int sp = 0; sp < 2; sp++) {
                const u16* r0 = &Qs[sp * 64 + mrow + g][0];
                const u16* r1 = &Qs[sp * 64 + mrow + 8 + g][0];
                a[sp][0] = *(const u32*)&r0[2 * w];
                a[sp][1] = *(const u32*)&r1[2 * w];
                a[sp][2] = *(const u32*)&r0[2 * (w + 4)];
                a[sp][3] = *(const u32*)&r1[2 * (w + 4)];
            }
            #pragma unroll
            for (int nt = 0; nt < 8; nt++) {
                const u16* kh = &Ks[nt * 8 + g][0];
                const u16* kl = &Ks[64 + nt * 8 + g][0];
                u32 bh0 = *(const u32*)&kh[2 * w], bh1 = *(const u32*)&kh[2 * (w + 4)];
                u32 bl0 = *(const u32*)&kl[2 * w], bl1 = *(const u32*)&kl[2 * (w + 4)];
                mma_bf16(s[nt], a[0][0], a[0][1], a[0][2], a[0][3], bh0, bh1);
                mma_bf16(s[nt], a[0][0], a[0][1], a[0][2], a[0][3], bl0, bl1);
                mma_bf16(s[nt], a[1][0], a[1][1], a[1][2], a[1][3], bh0, bh1);
            }
        }

        // ---- online softmax (rows g, g+8 of this warp's strip) ----
        float rm0 = -1e30f, rm1 = -1e30f;
        #pragma unroll
        for (int nt = 0; nt < 8; nt++) {
            rm0 = fmaxf(rm0, fmaxf(s[nt][0], s[nt][1]));
            rm1 = fmaxf(rm1, fmaxf(s[nt][2], s[nt][3]));
        }
        rm0 = fmaxf(rm0, __shfl_xor_sync(0xffffffffu, rm0, 1));
        rm0 = fmaxf(rm0, __shfl_xor_sync(0xffffffffu, rm0, 2));
        rm1 = fmaxf(rm1, __shfl_xor_sync(0xffffffffu, rm1, 1));
        rm1 = fmaxf(rm1, __shfl_xor_sync(0xffffffffu, rm1, 2));

        const float mn0 = fmaxf(mx0, rm0);
        const float mn1 = fmaxf(mx1, rm1);
        const float corr0 = __expf(mx0 - mn0);
        const float corr1 = __expf(mx1 - mn1);
        float rs0 = 0.f, rs1 = 0.f;
        #pragma unroll
        for (int nt = 0; nt < 8; nt++) {
            s[nt][0] = __expf(s[nt][0] - mn0); rs0 += s[nt][0];
            s[nt][1] = __expf(s[nt][1] - mn0); rs0 += s[nt][1];
            s[nt][2] = __expf(s[nt][2] - mn1); rs1 += s[nt][2];
            s[nt][3] = __expf(s[nt][3] - mn1); rs1 += s[nt][3];
        }
        rs0 += __shfl_xor_sync(0xffffffffu, rs0, 1);
        rs0 += __shfl_xor_sync(0xffffffffu, rs0, 2);
        rs1 += __shfl_xor_sync(0xffffffffu, rs1, 1);
        rs1 += __shfl_xor_sync(0xffffffffu, rs1, 2);
        lsum0 = lsum0 * corr0 + rs0; mx0 = mn0;
        lsum1 = lsum1 * corr1 + rs1; mx1 = mn1;
        #pragma unroll
        for (int nt = 0; nt < 8; nt++) {
            acc[nt][0] *= corr0; acc[nt][1] *= corr0;
            acc[nt][2] *= corr1; acc[nt][3] *= corr1;
        }

        // ---- O += P V (P in regs: C-frag pair == A-frag; hi/lo split) ----
        #pragma unroll
        for (int kc = 0; kc < 4; kc++) {
            const int j0 = 2 * kc, j1 = 2 * kc + 1;
            float ph[8], pl[8];
            #pragma unroll
            for (int r = 0; r < 4; r++) { split_bf16(s[j0][r], ph[r],     pl[r]); }
            #pragma unroll
            for (int r = 0; r < 4; r++) { split_bf16(s[j1][r], ph[4 + r], pl[4 + r]); }
            u32 pah[4], pal[4];
            pah[0] = pack_bf16(ph[0], ph[1]); pal[0] = pack_bf16(pl[0], pl[1]);
            pah[1] = pack_bf16(ph[2], ph[3]); pal[1] = pack_bf16(pl[2], pl[3]);
            pah[2] = pack_bf16(ph[4], ph[5]); pal[2] = pack_bf16(pl[4], pl[5]);
            pah[3] = pack_bf16(ph[6], ph[7]); pal[3] = pack_bf16(pl[6], pl[7]);

            const int w = kc * 8 + tg;
            #pragma unroll
            for (int nt = 0; nt < 8; nt++) {
                const u16* vh = &Vs[nt * 8 + g][0];
                const u16* vl = &Vs[64 + nt * 8 + g][0];
                u32 bh0 = *(const u32*)&vh[2 * w], bh1 = *(const u32*)&vh[2 * (w + 4)];
                u32 bl0 = *(const u32*)&vl[2 * w], bl1 = *(const u32*)&vl[2 * (w + 4)];
                mma_bf16(acc[nt], pah[0], pah[1], pah[2], pah[3], bh0, bh1);
                mma_bf16(acc[nt], pah[0], pah[1], pah[2], pah[3], bl0, bl1);
                mma_bf16(acc[nt], pal[0], pal[1], pal[2], pal[3], bh0, bh1);
            }
        }
    }

    const float inv0 = 1.0f / lsum0;
    const float inv1 = 1.0f / lsum1;
    float* Ob = O + (size_t)(b * Tq + qt * 64 + mrow) * ldo + ooff + h * HD_;
    #pragma unroll
    for (int nt = 0; nt < 8; nt++) {
        const int col = nt * 8 + 2 * tg;
        *(float2*)(Ob + (size_t)g * ldo + col) =
            make_float2(acc[nt][0] * inv0, acc[nt][1] * inv0);
        *(float2*)(Ob + (size_t)(g + 8) * ldo + col) =
            make_float2(acc[nt][2] * inv1, acc[nt][3] * inv1);
    }
}

// ---------------------------------------------------------------------------
// Shifted copy for slow path
// ---------------------------------------------------------------------------
__global__ void shift_kernel(const float* __restrict__ src, float* __restrict__ dst)
{
    const int e = blockIdx.x * 256 + threadIdx.x;
    if (e >= B_ * TS_ * D2_) return;
    const int t = (e / D2_) % TS_;
    dst[e] = (t == 0) ? 0.f : src[e - D2_];
}

// ---------------------------------------------------------------------------
// Host orchestration
// ---------------------------------------------------------------------------
extern "C" void kernel_launch(void* const* d_in, const int* in_sizes, int n_in,
                              void* d_out, int out_size)
{
    (void)in_sizes; (void)n_in; (void)out_size;

    const float* x_fast      = (const float*)d_in[0];
    const float* x_slow      = (const float*)d_in[1];
    const float* fself_wqkv  = (const float*)d_in[2];
    const float* fself_bqkv  = (const float*)d_in[3];
    const float* fself_wo    = (const float*)d_in[4];
    const float* fself_bo    = (const float*)d_in[5];
    const float* fcross_wqkv = (const float*)d_in[6];
    const float* fcross_bqkv = (const float*)d_in[7];
    const float* fcross_wo   = (const float*)d_in[8];
    const float* fcross_bo   = (const float*)d_in[9];
    const float* sself_wqkv  = (const float*)d_in[10];
    const float* sself_bqkv  = (const float*)d_in[11];
    const float* sself_wo    = (const float*)d_in[12];
    const float* sself_bo    = (const float*)d_in[13];
    const float* scross_wqkv = (const float*)d_in[14];
    const float* scross_bqkv = (const float*)d_in[15];
    const float* scross_wo   = (const float*)d_in[16];
    const float* scross_bo   = (const float*)d_in[17];
    const float* lift_w      = (const float*)d_in[18];
    const float* lift_b      = (const float*)d_in[19];
    const float* pool_w1     = (const float*)d_in[20];
    const float* pool_b1     = (const float*)d_in[21];
    const float* pool_w2     = (const float*)d_in[22];
    const float* pool_b2     = (const float*)d_in[23];

    float* out = (float*)d_out;
    float* zf = out;
    float* zs = out + (size_t)B_ * LF_ * 1024;

    float* S0 = nullptr;
    cudaGetSymbolAddress((void**)&S0, g_scratch);
    float* y     = S0 + O_Y;
    float* qkv_f = S0 + O_QKV_F;
    float* q_fc  = S0 + O_Q_FC;
    float* kv_fc = S0 + O_KV_FC;
    float* o1    = S0 + O_O1;
    float* o2    = S0 + O_O2;
    float* h1    = S0 + O_H1;
    float* s     = S0 + O_S;
    float* ss    = S0 + O_SS;
    float* qkv_s = S0 + O_QKV_S;
    float* q_sc  = S0 + O_Q_SC;
    float* kv_sc = S0 + O_KV_SC;
    float* o3    = S0 + O_O3;
    float* o4    = S0 + O_O4;

    cudaFuncSetAttribute(attn_mma_kernel,
                         cudaFuncAttributeMaxDynamicSharedMemorySize, SMEM_ATTN_MMA);

    const float scale = 0.125f;  // 1/sqrt(64)

    // 1) lift: (1024 x 512, K=1024)
    gemm_bf16_kernel<<<dim3(8, 8), 256>>>(x_slow, 1024, 0, lift_w, 512, 0, lift_b,
                                          y, 512, 0, 1024, 512, 1024, 0);
    // 2) fself qkv: (4096 x 1536, K=512)
    gemm_bf16_kernel<<<dim3(24, 32), 256>>>(x_fast, 1024, 0, fself_wqkv, 1536, 0, fself_bqkv,
                                            qkv_f, 1536, 0, 4096, 1536, 512, 0);
    // 3) fcross q: (4096 x 512, K=512)
    gemm_bf16_kernel<<<dim3(8, 32), 256>>>(x_fast, 1024, 512, fcross_wqkv, 1536, 0, fcross_bqkv,
                                           q_fc, 512, 0, 4096, 512, 512, 0);
    // 4) fcross kv on deduped y: (1024 x 1024, K=512)
    gemm_bf16_kernel<<<dim3(16, 8), 256>>>(y, 512, 0, fcross_wqkv, 1536, 512, fcross_bqkv + 512,
                                           kv_fc, 1024, 0, 1024, 1024, 512, 0);
    // 9) pool MLP layer 1 (+GELU): (1024 x 2048, K=4096)
    gemm_bf16_kernel<<<dim3(32, 8), 256>>>(x_fast, 4096, 0, pool_w1, 2048, 0, pool_b1,
                                           h1, 2048, 0, 1024, POOLH, 4096, 1);
    // 5) fself attention (Tq=Tk=2048)
    attn_mma_kernel<<<dim3(32, H_, B_), 128, SMEM_ATTN_MMA>>>(
        qkv_f, 1536, 0, qkv_f, 1536, 512, qkv_f, 1536, 1024,
        o1, 512, 0, LF_, LF_, scale);
    // 6) fcross attention (Tq=2048, Tk=512)
    attn_mma_kernel<<<dim3(32, H_, B_), 128, SMEM_ATTN_MMA>>>(
        q_fc, 512, 0, kv_fc, 1024, 0, kv_fc, 1024, 512,
        o2, 512, 0, LF_, TS_, scale);
    // 7) fself out-proj
    gemm_bf16_kernel<<<dim3(8, 32), 256>>>(o1, 512, 0, fself_wo, 512, 0, fself_bo,
                                           zf, 1024, 0, 4096, 512, 512, 0);
    // 8) fcross out-proj
    gemm_bf16_kernel<<<dim3(8, 32), 256>>>(o2, 512, 0, fcross_wo, 512, 0, fcross_bo,
                                           zf, 1024, 512, 4096, 512, 512, 0);
    // 10) pool MLP layer 2: (1024 x 512, K=2048)
    gemm_bf16_kernel<<<dim3(8, 8), 256>>>(h1, 2048, 0, pool_w2, 512, 0, pool_b2,
                                          s, 512, 0, 1024, 512, 2048, 0);
    // 11) shift
    shift_kernel<<<(B_ * TS_ * D2_ + 255) / 256, 256>>>(s, ss);
    // 12) sself qkv: (1024 x 1536, K=512)
    gemm_bf16_kernel<<<dim3(24, 8), 256>>>(x_slow, 1024, 0, sself_wqkv, 1536, 0, sself_bqkv,
                                           qkv_s, 1536, 0, 1024, 1536, 512, 0);
    // 13) scross q
    gemm_bf16_kernel<<<dim3(8, 8), 256>>>(x_slow, 1024, 512, scross_wqkv, 1536, 0, scross_bqkv,
                                          q_sc, 512, 0, 1024, 512, 512, 0);
    // 14) scross kv
    gemm_bf16_kernel<<<dim3(16, 8), 256>>>(ss, 512, 0, scross_wqkv, 1536, 512, scross_bqkv + 512,
                                           kv_sc, 1024, 0, 1024, 1024, 512, 0);
    // 15) sself attention (Tq=Tk=512)
    attn_mma_kernel<<<dim3(8, H_, B_), 128, SMEM_ATTN_MMA>>>(
        qkv_s, 1536, 0, qkv_s, 1536, 512, qkv_s, 1536, 1024,
        o3, 512, 0, TS_, TS_, scale);
    // 16) scross attention (Tq=Tk=512)
    attn_mma_kernel<<<dim3(8, H_, B_), 128, SMEM_ATTN_MMA>>>(
        q_sc, 512, 0, kv_sc, 1024, 0, kv_sc, 1024, 512,
        o4, 512, 0, TS_, TS_, scale);
    // 17) sself out-proj
    gemm_bf16_kernel<<<dim3(8, 8), 256>>>(o3, 512, 0, sself_wo, 512, 0, sself_bo,
                                          zs, 1024, 0, 1024, 512, 512, 0);
    // 18) scross out-proj
    gemm_bf16_kernel<<<dim3(8, 8), 256>>>(o4, 512, 0, scross_wo, 512, 0, scross_bo,
                                          zs, 1024, 512, 1024, 512, 512, 0);
}

// round 5
// speedup vs baseline: 2.1430x; 1.3402x over previous
#include <cuda_runtime.h>
#include <cuda_bf16.h>
#include <math.h>

#define B_    2
#define LF_   2048
#define TS_   512
#define D2_   512
#define H_    8
#define HD_   64
#define POOLH 2048

typedef unsigned long long u64;
typedef unsigned int u32;
typedef unsigned short u16;

// ---------------------------------------------------------------------------
// bf16 split + pack helpers
// ---------------------------------------------------------------------------
__device__ __forceinline__ void split_bf16(float x, float &hi, float &lo) {
    hi = __bfloat162float(__float2bfloat16(x));
    lo = x - hi;
}
__device__ __forceinline__ u32 pack_bf16(float a, float b) {
    __nv_bfloat162 t = __floats2bfloat162_rn(a, b);
    return *(u32*)&t;
}
__device__ __forceinline__ u16 bf16_bits(float a) {
    __nv_bfloat16 t = __float2bfloat16(a);
    return *(u16*)&t;
}
__device__ __forceinline__ void mma_bf16(float c[4], u32 a0, u32 a1, u32 a2, u32 a3,
                                         u32 b0, u32 b1) {
    asm volatile(
        "mma.sync.aligned.m16n8k16.row.col.f32.bf16.bf16.f32 "
        "{%0,%1,%2,%3}, {%4,%5,%6,%7}, {%8,%9}, {%0,%1,%2,%3};\n"
        : "+f"(c[0]), "+f"(c[1]), "+f"(c[2]), "+f"(c[3])
        : "r"(a0), "r"(a1), "r"(a2), "r"(a3), "r"(b0), "r"(b1));
}

// ---------------------------------------------------------------------------
// Scratch
// ---------------------------------------------------------------------------
static const size_t O_Y     = 0;
static const size_t O_QKV_F = O_Y     + 524288;
static const size_t O_Q_FC  = O_QKV_F + 6291456;
static const size_t O_KV_FC = O_Q_FC  + 2097152;
static const size_t O_O1    = O_KV_FC + 1048576;
static const size_t O_O2    = O_O1    + 2097152;
static const size_t O_H1    = O_O2    + 2097152;
static const size_t O_S     = O_H1    + 2097152;
static const size_t O_QKV_S = O_S     + 524288;
static const size_t O_Q_SC  = O_QKV_S + 1572864;
static const size_t O_KV_SC = O_Q_SC  + 524288;
static const size_t O_O3    = O_KV_SC + 1048576;
static const size_t O_O4    = O_O3    + 524288;
static const size_t SCRATCH_FLOATS = O_O4 + 524288;

__device__ float g_scratch[SCRATCH_FLOATS];

// ---------------------------------------------------------------------------
// Batched multi-problem GEMM, double-buffered smem, split-bf16 tensor cores.
// Per problem: C[m, coff+n] = act( A[m, aoff+k] * W[k, woff+n] + bias[n] )
// Block tile 128x64, K-chunk 32, 256 threads (8 warps 4x2), warp tile 32x32.
// ashift=1: A row r reads row r-1, zero when (r % 512)==0 (slow-path delay).
// ---------------------------------------------------------------------------
#define GD_MAX 6
struct GemmDesc {
    const float *A, *W, *bias;
    float *C;
    int lda, aoff, ldw, woff, ldc, coff, K, act, ashift, nbx, blk0;
};
struct GemmBatch { GemmDesc d[GD_MAX]; int n; };

#define GS_STRIDE 40
#define G_ABUF (128 * 2 * GS_STRIDE)            // 10240 u16 (hi+lo)
#define G_WBUF (64 * 2 * GS_STRIDE)             // 5120 u16
#define G_BUF  (G_ABUF + G_WBUF)                // 15360 u16 per stage
#define SMEM_GEMM (2 * G_BUF * 2)               // bytes (61440)

__global__ __launch_bounds__(256) void gemm_batch_kernel(GemmBatch batch)
{
    extern __shared__ __align__(16) u16 smg[];

    int pi = 0;
    #pragma unroll
    for (int i = 1; i < GD_MAX; i++)
        if (i < batch.n && (int)blockIdx.x >= batch.d[i].blk0) pi = i;
    const GemmDesc D = batch.d[pi];
    const int lb = blockIdx.x - D.blk0;
    const int m0 = (lb / D.nbx) * 128;
    const int n0 = (lb % D.nbx) * 64;

    const int tid  = threadIdx.x;
    const int lane = tid & 31;
    const int warp = tid >> 5;
    const int warp_m = warp >> 1;
    const int warp_n = warp & 1;
    const int g  = lane >> 2;
    const int tg = lane & 3;

    float acc[2][4][4];
    #pragma unroll
    for (int mt = 0; mt < 2; mt++)
        #pragma unroll
        for (int nt = 0; nt < 4; nt++)
            #pragma unroll
            for (int r = 0; r < 4; r++) acc[mt][nt][r] = 0.f;

    const int a_row = tid >> 3;
    const int a_kc  = (tid & 7) * 4;
    const int w_k   = tid >> 4;
    const int w_n4  = (tid & 15) * 4;

    float4 av[4], wv[2];

    auto load_regs = [&](int k0) {
        #pragma unroll
        for (int p = 0; p < 4; p++) {
            const int mg = m0 + a_row + 32 * p;
            if (D.ashift) {
                if ((mg & 511) == 0)
                    av[p] = make_float4(0.f, 0.f, 0.f, 0.f);
                else
                    av[p] = *(const float4*)(D.A + (size_t)(mg - 1) * D.lda + D.aoff + k0 + a_kc);
            } else {
                av[p] = *(const float4*)(D.A + (size_t)mg * D.lda + D.aoff + k0 + a_kc);
            }
        }
        #pragma unroll
        for (int p = 0; p < 2; p++)
            wv[p] = *(const float4*)(D.W + (size_t)(k0 + w_k + 16 * p) * D.ldw + D.woff + n0 + w_n4);
    };

    auto store_tiles = [&](u16* As, u16* Ws) {
        #pragma unroll
        for (int p = 0; p < 4; p++) {
            const int m = a_row + 32 * p;
            float hx, lx, hy, ly, hz, lz, hw, lw;
            split_bf16(av[p].x, hx, lx); split_bf16(av[p].y, hy, ly);
            split_bf16(av[p].z, hz, lz); split_bf16(av[p].w, hw, lw);
            u16* rh = &As[(size_t)m * GS_STRIDE + a_kc];
            u16* rl = &As[(size_t)(128 + m) * GS_STRIDE + a_kc];
            *(u32*)&rh[0] = pack_bf16(hx, hy);
            *(u32*)&rh[2] = pack_bf16(hz, hw);
            *(u32*)&rl[0] = pack_bf16(lx, ly);
            *(u32*)&rl[2] = pack_bf16(lz, lw);
        }
        #pragma unroll
        for (int p = 0; p < 2; p++) {
            const int k = w_k + 16 * p;
            const float vals[4] = {wv[p].x, wv[p].y, wv[p].z, wv[p].w};
            #pragma unroll
            for (int j = 0; j < 4; j++) {
                float hi, lo;
                split_bf16(vals[j], hi, lo);
                Ws[(size_t)(w_n4 + j) * GS_STRIDE + k]      = bf16_bits(hi);
                Ws[(size_t)(64 + w_n4 + j) * GS_STRIDE + k] = bf16_bits(lo);
            }
        }
    };

    auto do_mma = [&](const u16* As, const u16* Ws) {
        #pragma unroll
        for (int kk = 0; kk < 2; kk++) {
            const int kw = kk * 8 + tg;
            u32 afr[2][2][4];
            #pragma unroll
            for (int s = 0; s < 2; s++)
                #pragma unroll
                for (int mt = 0; mt < 2; mt++) {
                    const int m = warp_m * 32 + mt * 16 + g;
                    const u16* r0 = &As[(size_t)(s * 128 + m) * GS_STRIDE];
                    const u16* r1 = &As[(size_t)(s * 128 + m + 8) * GS_STRIDE];
                    afr[s][mt][0] = *(const u32*)&r0[2 * kw];
                    afr[s][mt][1] = *(const u32*)&r1[2 * kw];
                    afr[s][mt][2] = *(const u32*)&r0[2 * (kw + 4)];
                    afr[s][mt][3] = *(const u32*)&r1[2 * (kw + 4)];
                }
            u32 bfr[2][4][2];
            #pragma unroll
            for (int s = 0; s < 2; s++)
                #pragma unroll
                for (int nt = 0; nt < 4; nt++) {
                    const int n = warp_n * 32 + nt * 8 + g;
                    const u16* r = &Ws[(size_t)(s * 64 + n) * GS_STRIDE];
                    bfr[s][nt][0] = *(const u32*)&r[2 * kw];
                    bfr[s][nt][1] = *(const u32*)&r[2 * (kw + 4)];
                }
            #pragma unroll
            for (int mt = 0; mt < 2; mt++)
                #pragma unroll
                for (int nt = 0; nt < 4; nt++) {
                    mma_bf16(acc[mt][nt], afr[0][mt][0], afr[0][mt][1], afr[0][mt][2], afr[0][mt][3],
                             bfr[0][nt][0], bfr[0][nt][1]);
                    mma_bf16(acc[mt][nt], afr[0][mt][0], afr[0][mt][1], afr[0][mt][2], afr[0][mt][3],
                             bfr[1][nt][0], bfr[1][nt][1]);
                    mma_bf16(acc[mt][nt], afr[1][mt][0], afr[1][mt][1], afr[1][mt][2], afr[1][mt][3],
                             bfr[0][nt][0], bfr[0][nt][1]);
                }
        }
    };

    // software pipeline: LDG(next) -> MMA(cur) -> STS(next) -> sync
    load_regs(0);
    store_tiles(smg, smg + G_ABUF);
    __syncthreads();

    const int nk = D.K >> 5;
    for (int ki = 0; ki < nk; ki++) {
        const int cur = ki & 1;
        const bool has_next = (ki + 1) < nk;
        if (has_next) load_regs((ki + 1) * 32);
        do_mma(smg + cur * G_BUF, smg + cur * G_BUF + G_ABUF);
        if (has_next) store_tiles(smg + (1 - cur) * G_BUF, smg + (1 - cur) * G_BUF + G_ABUF);
        __syncthreads();
    }

    #pragma unroll
    for (int mt = 0; mt < 2; mt++) {
        #pragma unroll
        for (int nt = 0; nt < 4; nt++) {
            const int m = m0 + warp_m * 32 + mt * 16 + g;
            const int n = n0 + warp_n * 32 + nt * 8 + tg * 2;
            const float bb0 = D.bias[n], bb1 = D.bias[n + 1];
            float v[4] = {acc[mt][nt][0] + bb0, acc[mt][nt][1] + bb1,
                          acc[mt][nt][2] + bb0, acc[mt][nt][3] + bb1};
            if (D.act == 1) {
                #pragma unroll
                for (int r = 0; r < 4; r++) {
                    float x = v[r];
                    float u = 0.7978845608028654f * (x + 0.044715f * x * x * x);
                    v[r] = 0.5f * x * (1.0f + tanhf(u));
                }
            }
            *(float2*)(D.C + (size_t)m * D.ldc + D.coff + n)       = make_float2(v[0], v[1]);
            *(float2*)(D.C + (size_t)(m + 8) * D.ldc + D.coff + n) = make_float2(v[2], v[3]);
        }
    }
}

// ---------------------------------------------------------------------------
// Batched flash attention on tensor cores (verified R3 body).
// 64 q-rows/CTA, 4 warps, 64-key tiles, P in registers. 128 threads.
// ---------------------------------------------------------------------------
#define AD_MAX 4
struct AttnDesc {
    const float *Q, *K, *V;
    float *O;
    int ldq, qoff, ldk, koff, ldv, voff, ldo, ooff, Tq, Tk, nbx, blk0;
};
struct AttnBatch { AttnDesc d[AD_MAX]; int n; };

#define AT_STRIDE 72
#define SMEM_ATTN_MMA (3 * 128 * AT_STRIDE * 2)

__global__ __launch_bounds__(128) void attn_batch_kernel(AttnBatch batch)
{
    extern __shared__ __align__(16) u16 smu[];
    u16 (*Qs)[AT_STRIDE] = (u16(*)[AT_STRIDE])smu;
    u16 (*Ks)[AT_STRIDE] = Qs + 128;
    u16 (*Vs)[AT_STRIDE] = Ks + 128;

    int pi = 0;
    #pragma unroll
    for (int i = 1; i < AD_MAX; i++)
        if (i < batch.n && (int)blockIdx.x >= batch.d[i].blk0) pi = i;
    const AttnDesc D = batch.d[pi];
    const int lb = blockIdx.x - D.blk0;
    const int qt = lb % D.nbx;
    const int h  = (lb / D.nbx) % H_;
    const int b  = lb / (D.nbx * H_);

    const float scale = 0.125f;
    const int tid  = threadIdx.x;
    const int lane = tid & 31;
    const int warp = tid >> 5;
    const int g  = lane >> 2;
    const int tg = lane & 3;
    const int mrow = warp * 16;

    const float* Qb = D.Q + (size_t)(b * D.Tq + qt * 64) * D.ldq + D.qoff + h * HD_;
    const float* Kb = D.K + (size_t)(b * D.Tk) * D.ldk + D.koff + h * HD_;
    const float* Vb = D.V + (size_t)(b * D.Tk) * D.ldv + D.voff + h * HD_;

    for (int e = tid; e < 64 * 16; e += 128) {
        const int r = e >> 4, c = (e & 15) * 4;
        float4 q4 = *(const float4*)(Qb + (size_t)r * D.ldq + c);
        float h0, l0, h1, l1, h2, l2, h3, l3;
        split_bf16(q4.x * scale, h0, l0); split_bf16(q4.y * scale, h1, l1);
        split_bf16(q4.z * scale, h2, l2); split_bf16(q4.w * scale, h3, l3);
        *(u32*)&Qs[r][c]          = pack_bf16(h0, h1);
        *(u32*)&Qs[r][c + 2]      = pack_bf16(h2, h3);
        *(u32*)&Qs[64 + r][c]     = pack_bf16(l0, l1);
        *(u32*)&Qs[64 + r][c + 2] = pack_bf16(l2, l3);
    }

    float acc[8][4];
    #pragma unroll
    for (int nt = 0; nt < 8; nt++)
        #pragma unroll
        for (int r = 0; r < 4; r++) acc[nt][r] = 0.f;
    float mx0 = -1e30f, mx1 = -1e30f, lsum0 = 0.f, lsum1 = 0.f;

    for (int kt = 0; kt < D.Tk; kt += 64) {
        __syncthreads();
        for (int e = tid; e < 64 * 16; e += 128) {
            const int r = e >> 4, c = (e & 15) * 4;
            float4 k4 = *(const float4*)(Kb + (size_t)(kt + r) * D.ldk + c);
            float h0, l0, h1, l1, h2, l2, h3, l3;
            split_bf16(k4.x, h0, l0); split_bf16(k4.y, h1, l1);
            split_bf16(k4.z, h2, l2); split_bf16(k4.w, h3, l3);
            *(u32*)&Ks[r][c]          = pack_bf16(h0, h1);
            *(u32*)&Ks[r][c + 2]      = pack_bf16(h2, h3);
            *(u32*)&Ks[64 + r][c]     = pack_bf16(l0, l1);
            *(u32*)&Ks[64 + r][c + 2] = pack_bf16(l2, l3);
            float4 v4 = *(const float4*)(Vb + (size_t)(kt + r) * D.ldv + c);
            float vh[4], vl[4];
            split_bf16(v4.x, vh[0], vl[0]); split_bf16(v4.y, vh[1], vl[1]);
            split_bf16(v4.z, vh[2], vl[2]); split_bf16(v4.w, vh[3], vl[3]);
            #pragma unroll
            for (int i = 0; i < 4; i++) {
                Vs[c + i][r]      = bf16_bits(vh[i]);
                Vs[64 + c + i][r] = bf16_bits(vl[i]);
            }
        }
        __syncthreads();

        float s[8][4];
        #pragma unroll
        for (int nt = 0; nt < 8; nt++)
            #pragma unroll
            for (int r = 0; r < 4; r++) s[nt][r] = 0.f;

        #pragma unroll
        for (int kc = 0; kc < 4; kc++) {
            const int w = kc * 8 + tg;
            u32 a[2][4];
            #pragma unroll
            for (int sp = 0; sp < 2; sp++) {
                const u16* r0 = &Qs[sp * 64 + mrow + g][0];
                const u16* r1 = &Qs[sp * 64 + mrow + 8 + g][0];
                a[sp][0] = *(const u32*)&r0[2 * w];
                a[sp][1] = *(const u32*)&r1[2 * w];
                a[sp][2] = *(const u32*)&r0[2 * (w + 4)];
                a[sp][3] = *(const u32*)&r1[2 * (w + 4)];
            }
            #pragma unroll
            for (int nt = 0; nt < 8; nt++) {
                const u16* kh = &Ks[nt * 8 + g][0];
                const u16* kl = &Ks[64 + nt * 8 + g][0];
                u32 bh0 = *(const u32*)&kh[2 * w], bh1 = *(const u32*)&kh[2 * (w + 4)];
                u32 bl0 = *(const u32*)&kl[2 * w], bl1 = *(const u32*)&kl[2 * (w + 4)];
                mma_bf16(s[nt], a[0][0], a[0][1], a[0][2], a[0][3], bh0, bh1);
                mma_bf16(s[nt], a[0][0], a[0][1], a[0][2], a[0][3], bl0, bl1);
                mma_bf16(s[nt], a[1][0], a[1][1], a[1][2], a[1][3], bh0, bh1);
            }
        }

        float rm0 = -1e30f, rm1 = -1e30f;
        #pragma unroll
        for (int nt = 0; nt < 8; nt++) {
            rm0 = fmaxf(rm0, fmaxf(s[nt][0], s[nt][1]));
            rm1 = fmaxf(rm1, fmaxf(s[nt][2], s[nt][3]));
        }
        rm0 = fmaxf(rm0, __shfl_xor_sync(0xffffffffu, rm0, 1));
        rm0 = fmaxf(rm0, __shfl_xor_sync(0xffffffffu, rm0, 2));
        rm1 = fmaxf(rm1, __shfl_xor_sync(0xffffffffu, rm1, 1));
        rm1 = fmaxf(rm1, __shfl_xor_sync(0xffffffffu, rm1, 2));

        const float mn0 = fmaxf(mx0, rm0);
        const float mn1 = fmaxf(mx1, rm1);
        const float corr0 = __expf(mx0 - mn0);
        const float corr1 = __expf(mx1 - mn1);
        float rs0 = 0.f, rs1 = 0.f;
        #pragma unroll
        for (int nt = 0; nt < 8; nt++) {
            s[nt][0] = __expf(s[nt][0] - mn0); rs0 += s[nt][0];
            s[nt][1] = __expf(s[nt][1] - mn0); rs0 += s[nt][1];
            s[nt][2] = __expf(s[nt][2] - mn1); rs1 += s[nt][2];
            s[nt][3] = __expf(s[nt][3] - mn1); rs1 += s[nt][3];
        }
        rs0 += __shfl_xor_sync(0xffffffffu, rs0, 1);
        rs0 += __shfl_xor_sync(0xffffffffu, rs0, 2);
        rs1 += __shfl_xor_sync(0xffffffffu, rs1, 1);
        rs1 += __shfl_xor_sync(0xffffffffu, rs1, 2);
        lsum0 = lsum0 * corr0 + rs0; mx0 = mn0;
        lsum1 = lsum1 * corr1 + rs1; mx1 = mn1;
        #pragma unroll
        for (int nt = 0; nt < 8; nt++) {
            acc[nt][0] *= corr0; acc[nt][1] *= corr0;
            acc[nt][2] *= corr1; acc[nt][3] *= corr1;
        }

        #pragma unroll
        for (int kc = 0; kc < 4; kc++) {
            const int j0 = 2 * kc, j1 = 2 * kc + 1;
            float ph[8], pl[8];
            #pragma unroll
            for (int r = 0; r < 4; r++) { split_bf16(s[j0][r], ph[r],     pl[r]); }
            #pragma unroll
            for (int r = 0; r < 4; r++) { split_bf16(s[j1][r], ph[4 + r], pl[4 + r]); }
            u32 pah[4], pal[4];
            pah[0] = pack_bf16(ph[0], ph[1]); pal[0] = pack_bf16(pl[0], pl[1]);
            pah[1] = pack_bf16(ph[2], ph[3]); pal[1] = pack_bf16(pl[2], pl[3]);
            pah[2] = pack_bf16(ph[4], ph[5]); pal[2] = pack_bf16(pl[4], pl[5]);
            pah[3] = pack_bf16(ph[6], ph[7]); pal[3] = pack_bf16(pl[6], pl[7]);

            const int w = kc * 8 + tg;
            #pragma unroll
            for (int nt = 0; nt < 8; nt++) {
                const u16* vh = &Vs[nt * 8 + g][0];
                const u16* vl = &Vs[64 + nt * 8 + g][0];
                u32 bh0 = *(const u32*)&vh[2 * w], bh1 = *(const u32*)&vh[2 * (w + 4)];
                u32 bl0 = *(const u32*)&vl[2 * w], bl1 = *(const u32*)&vl[2 * (w + 4)];
                mma_bf16(acc[nt], pah[0], pah[1], pah[2], pah[3], bh0, bh1);
                mma_bf16(acc[nt], pah[0], pah[1], pah[2], pah[3], bl0, bl1);
                mma_bf16(acc[nt], pal[0], pal[1], pal[2], pal[3], bh0, bh1);
            }
        }
    }

    const float inv0 = 1.0f / lsum0;
    const float inv1 = 1.0f / lsum1;
    float* Ob = D.O + (size_t)(b * D.Tq + qt * 64 + mrow) * D.ldo + D.ooff + h * HD_;
    #pragma unroll
    for (int nt = 0; nt < 8; nt++) {
        const int col = nt * 8 + 2 * tg;
        *(float2*)(Ob + (size_t)g * D.ldo + col) =
            make_float2(acc[nt][0] * inv0, acc[nt][1] * inv0);
        *(float2*)(Ob + (size_t)(g + 8) * D.ldo + col) =
            make_float2(acc[nt][2] * inv1, acc[nt][3] * inv1);
    }
}

// ---------------------------------------------------------------------------
// Host orchestration: 5 launches
// ---------------------------------------------------------------------------
static inline GemmDesc mk_gemm(const float* A, int lda, int aoff,
                               const float* W, int ldw, int woff,
                               const float* bias, float* C, int ldc, int coff,
                               int M, int N, int K, int act, int ashift,
                               int& blk_cursor)
{
    GemmDesc d;
    d.A = A; d.W = W; d.bias = bias; d.C = C;
    d.lda = lda; d.aoff = aoff; d.ldw = ldw; d.woff = woff;
    d.ldc = ldc; d.coff = coff; d.K = K; d.act = act; d.ashift = ashift;
    d.nbx = N / 64; d.blk0 = blk_cursor;
    blk_cursor += (N / 64) * (M / 128);
    return d;
}

static inline AttnDesc mk_attn(const float* Q, int ldq, int qoff,
                               const float* K, int ldk, int koff,
                               const float* V, int ldv, int voff,
                               float* O, int ldo, int ooff,
                               int Tq, int Tk, int& blk_cursor)
{
    AttnDesc d;
    d.Q = Q; d.K = K; d.V = V; d.O = O;
    d.ldq = ldq; d.qoff = qoff; d.ldk = ldk; d.koff = koff;
    d.ldv = ldv; d.voff = voff; d.ldo = ldo; d.ooff = ooff;
    d.Tq = Tq; d.Tk = Tk; d.nbx = Tq / 64; d.blk0 = blk_cursor;
    blk_cursor += (Tq / 64) * H_ * B_;
    return d;
}

extern "C" void kernel_launch(void* const* d_in, const int* in_sizes, int n_in,
                              void* d_out, int out_size)
{
    (void)in_sizes; (void)n_in; (void)out_size;

    const float* x_fast      = (const float*)d_in[0];
    const float* x_slow      = (const float*)d_in[1];
    const float* fself_wqkv  = (const float*)d_in[2];
    const float* fself_bqkv  = (const float*)d_in[3];
    const float* fself_wo    = (const float*)d_in[4];
    const float* fself_bo    = (const float*)d_in[5];
    const float* fcross_wqkv = (const float*)d_in[6];
    const float* fcross_bqkv = (const float*)d_in[7];
    const float* fcross_wo   = (const float*)d_in[8];
    const float* fcross_bo   = (const float*)d_in[9];
    const float* sself_wqkv  = (const float*)d_in[10];
    const float* sself_bqkv  = (const float*)d_in[11];
    const float* sself_wo    = (const float*)d_in[12];
    const float* sself_bo    = (const float*)d_in[13];
    const float* scross_wqkv = (const float*)d_in[14];
    const float* scross_bqkv = (const float*)d_in[15];
    const float* scross_wo   = (const float*)d_in[16];
    const float* scross_bo   = (const float*)d_in[17];
    const float* lift_w      = (const float*)d_in[18];
    const float* lift_b      = (const float*)d_in[19];
    const float* pool_w1     = (const float*)d_in[20];
    const float* pool_b1     = (const float*)d_in[21];
    const float* pool_w2     = (const float*)d_in[22];
    const float* pool_b2     = (const float*)d_in[23];

    float* out = (float*)d_out;
    float* zf = out;
    float* zs = out + (size_t)B_ * LF_ * 1024;

    float* S0 = nullptr;
    cudaGetSymbolAddress((void**)&S0, g_scratch);
    float* y     = S0 + O_Y;
    float* qkv_f = S0 + O_QKV_F;
    float* q_fc  = S0 + O_Q_FC;
    float* kv_fc = S0 + O_KV_FC;
    float* o1    = S0 + O_O1;
    float* o2    = S0 + O_O2;
    float* h1    = S0 + O_H1;
    float* s     = S0 + O_S;
    float* qkv_s = S0 + O_QKV_S;
    float* q_sc  = S0 + O_Q_SC;
    float* kv_sc = S0 + O_KV_SC;
    float* o3    = S0 + O_O3;
    float* o4    = S0 + O_O4;

    cudaFuncSetAttribute(gemm_batch_kernel,
                         cudaFuncAttributeMaxDynamicSharedMemorySize, SMEM_GEMM);
    cudaFuncSetAttribute(attn_batch_kernel,
                         cudaFuncAttributeMaxDynamicSharedMemorySize, SMEM_ATTN_MMA);

    // ---- L1: input-only GEMMs ----
    {
        GemmBatch gb; int cur = 0;
        gb.d[0] = mk_gemm(x_fast, 1024, 0,   fself_wqkv, 1536, 0, fself_bqkv,        qkv_f, 1536, 0, 4096, 1536, 512, 0, 0, cur);
        gb.d[1] = mk_gemm(x_fast, 4096, 0,   pool_w1,    2048, 0, pool_b1,           h1,    2048, 0, 1024, POOLH, 4096, 1, 0, cur);
        gb.d[2] = mk_gemm(x_fast, 1024, 512, fcross_wqkv, 1536, 0, fcross_bqkv,      q_fc,  512,  0, 4096, 512,  512, 0, 0, cur);
        gb.d[3] = mk_gemm(x_slow, 1024, 0,   lift_w,     512,  0, lift_b,            y,     512,  0, 1024, 512,  1024, 0, 0, cur);
        gb.d[4] = mk_gemm(x_slow, 1024, 0,   sself_wqkv, 1536, 0, sself_bqkv,        qkv_s, 1536, 0, 1024, 1536, 512, 0, 0, cur);
        gb.d[5] = mk_gemm(x_slow, 1024, 512, scross_wqkv, 1536, 0, scross_bqkv,      q_sc,  512,  0, 1024, 512,  512, 0, 0, cur);
        gb.n = 6;
        gemm_batch_kernel<<<cur, 256, SMEM_GEMM>>>(gb);
    }
    // ---- L2: kv_fc (needs y) + pool2 (needs h1) ----
    {
        GemmBatch gb; int cur = 0;
        gb.d[0] = mk_gemm(y,  512,  0, fcross_wqkv, 1536, 512, fcross_bqkv + 512, kv_fc, 1024, 0, 1024, 1024, 512,  0, 0, cur);
        gb.d[1] = mk_gemm(h1, 2048, 0, pool_w2,     512,  0,   pool_b2,           s,     512,  0, 1024, 512,  2048, 0, 0, cur);
        gb.n = 2;
        gemm_batch_kernel<<<cur, 256, SMEM_GEMM>>>(gb);
    }
    // ---- L3: kv_sc on shifted s (shift folded into A-load) ----
    {
        GemmBatch gb; int cur = 0;
        gb.d[0] = mk_gemm(s, 512, 0, scross_wqkv, 1536, 512, scross_bqkv + 512, kv_sc, 1024, 0, 1024, 1024, 512, 0, 1, cur);
        gb.n = 1;
        gemm_batch_kernel<<<cur, 256, SMEM_GEMM>>>(gb);
    }
    // ---- L4: all four attentions ----
    {
        AttnBatch ab; int cur = 0;
        ab.d[0] = mk_attn(qkv_f, 1536, 0, qkv_f, 1536, 512, qkv_f, 1536, 1024, o1, 512, 0, LF_, LF_, cur);
        ab.d[1] = mk_attn(q_fc,  512,  0, kv_fc, 1024, 0,   kv_fc, 1024, 512,  o2, 512, 0, LF_, TS_, cur);
        ab.d[2] = mk_attn(qkv_s, 1536, 0, qkv_s, 1536, 512, qkv_s, 1536, 1024, o3, 512, 0, TS_, TS_, cur);
        ab.d[3] = mk_attn(q_sc,  512,  0, kv_sc, 1024, 0,   kv_sc, 1024, 512,  o4, 512, 0, TS_, TS_, cur);
        ab.n = 4;
        attn_batch_kernel<<<cur, 128, SMEM_ATTN_MMA>>>(ab);
    }
    // ---- L5: all four out-projections ----
    {
        GemmBatch gb; int cur = 0;
        gb.d[0] = mk_gemm(o1, 512, 0, fself_wo,  512, 0, fself_bo,  zf, 1024, 0,   4096, 512, 512, 0, 0, cur);
        gb.d[1] = mk_gemm(o2, 512, 0, fcross_wo, 512, 0, fcross_bo, zf, 1024, 512, 4096, 512, 512, 0, 0, cur);
        gb.d[2] = mk_gemm(o3, 512, 0, sself_wo,  512, 0, sself_bo,  zs, 1024, 0,   1024, 512, 512, 0, 0, cur);
        gb.d[3] = mk_gemm(o4, 512, 0, scross_wo, 512, 0, scross_bo, zs, 1024, 512, 1024, 512, 512, 0, 0, cur);
        gb.n = 4;
        gemm_batch_kernel<<<cur, 256, SMEM_GEMM>>>(gb);
    }
}

// round 6
// speedup vs baseline: 3.3845x; 1.5794x over previous
#include <cuda_runtime.h>
#include <cuda_bf16.h>
#include <math.h>

#define B_    2
#define LF_   2048
#define TS_   512
#define D2_   512
#define H_    8
#define HD_   64
#define POOLH 2048

typedef unsigned long long u64;
typedef unsigned int u32;
typedef unsigned short u16;

// ---------------------------------------------------------------------------
// bf16 split/pack + MMA + ldmatrix helpers
// ---------------------------------------------------------------------------
__device__ __forceinline__ void split_bf16(float x, float &hi, float &lo) {
    hi = __bfloat162float(__float2bfloat16(x));
    lo = x - hi;
}
__device__ __forceinline__ u32 pack_bf16(float a, float b) {
    __nv_bfloat162 t = __floats2bfloat162_rn(a, b);
    return *(u32*)&t;
}
__device__ __forceinline__ u64 pack4_bf16(float a, float b, float c, float d) {
    return (u64)pack_bf16(a, b) | ((u64)pack_bf16(c, d) << 32);
}
__device__ __forceinline__ void mma_bf16(float c[4], u32 a0, u32 a1, u32 a2, u32 a3,
                                         u32 b0, u32 b1) {
    asm volatile(
        "mma.sync.aligned.m16n8k16.row.col.f32.bf16.bf16.f32 "
        "{%0,%1,%2,%3}, {%4,%5,%6,%7}, {%8,%9}, {%0,%1,%2,%3};\n"
        : "+f"(c[0]), "+f"(c[1]), "+f"(c[2]), "+f"(c[3])
        : "r"(a0), "r"(a1), "r"(a2), "r"(a3), "r"(b0), "r"(b1));
}
__device__ __forceinline__ u32 smaddr(const void* p) {
    return (u32)__cvta_generic_to_shared(p);
}
__device__ __forceinline__ void ldsm4(u32 r[4], u32 addr) {
    asm volatile("ldmatrix.sync.aligned.m8n8.x4.shared.b16 {%0,%1,%2,%3}, [%4];"
                 : "=r"(r[0]), "=r"(r[1]), "=r"(r[2]), "=r"(r[3]) : "r"(addr));
}
__device__ __forceinline__ void ldsm4t(u32 r[4], u32 addr) {
    asm volatile("ldmatrix.sync.aligned.m8n8.x4.trans.shared.b16 {%0,%1,%2,%3}, [%4];"
                 : "=r"(r[0]), "=r"(r[1]), "=r"(r[2]), "=r"(r[3]) : "r"(addr));
}

// ---------------------------------------------------------------------------
// Scratch
// ---------------------------------------------------------------------------
static const size_t O_Y     = 0;
static const size_t O_QKV_F = O_Y     + 524288;
static const size_t O_Q_FC  = O_QKV_F + 6291456;
static const size_t O_KV_FC = O_Q_FC  + 2097152;
static const size_t O_O1    = O_KV_FC + 1048576;
static const size_t O_O2    = O_O1    + 2097152;
static const size_t O_H1    = O_O2    + 2097152;
static const size_t O_S     = O_H1    + 2097152;
static const size_t O_QKV_S = O_S     + 524288;
static const size_t O_Q_SC  = O_QKV_S + 1572864;
static const size_t O_KV_SC = O_Q_SC  + 524288;
static const size_t O_O3    = O_KV_SC + 1048576;
static const size_t O_O4    = O_O3    + 524288;
static const size_t SCRATCH_FLOATS = O_O4 + 524288;

__device__ float g_scratch[SCRATCH_FLOATS];

// ---------------------------------------------------------------------------
// Batched multi-problem GEMM, double-buffered, split-bf16 tensor cores, LDSM.
// A tile: [hi/lo 128 rows each][k], stride 40. W tile: [hi/lo 32 k-rows][n],
// stride 72, natural [k][n] orientation; B-frags via ldmatrix.trans.
// ---------------------------------------------------------------------------
#define GD_MAX 6
struct GemmDesc {
    const float *A, *W, *bias;
    float *C;
    int lda, aoff, ldw, woff, ldc, coff, K, act, ashift, nbx, blk0;
};
struct GemmBatch { GemmDesc d[GD_MAX]; int n; };

#define GS_STRIDE 40
#define GW_STRIDE 72
#define G_ABUF (256 * GS_STRIDE)                 // 10240 u16 (hi+lo)
#define G_WBUF (64 * GW_STRIDE)                  // 4608 u16 (32 hi + 32 lo k-rows)
#define G_BUF  (G_ABUF + G_WBUF)                 // 14848 u16 per stage
#define SMEM_GEMM (2 * G_BUF * 2)                // 59392 bytes

__global__ __launch_bounds__(256) void gemm_batch_kernel(GemmBatch batch)
{
    extern __shared__ __align__(16) u16 smg[];

    int pi = 0;
    #pragma unroll
    for (int i = 1; i < GD_MAX; i++)
        if (i < batch.n && (int)blockIdx.x >= batch.d[i].blk0) pi = i;
    const GemmDesc D = batch.d[pi];
    const int lb = blockIdx.x - D.blk0;
    const int m0 = (lb / D.nbx) * 128;
    const int n0 = (lb % D.nbx) * 64;

    const int tid  = threadIdx.x;
    const int lane = tid & 31;
    const int warp = tid >> 5;
    const int warp_m = warp >> 1;
    const int warp_n = warp & 1;
    const int g  = lane >> 2;
    const int tg = lane & 3;

    // LDSM lane-address components
    const int l15 = lane & 15;
    const int l7  = lane & 7;
    const int ka8 = (lane >> 4) * 8;        // A: col offset for matrices 2,3
    const int wk8 = ((lane >> 3) & 1) * 8;  // W(trans): k-row offset for m1,m3
    const int wn8 = (lane >> 4) * 8;        // W(trans): n offset for m2,m3

    float acc[2][4][4];
    #pragma unroll
    for (int mt = 0; mt < 2; mt++)
        #pragma unroll
        for (int nt = 0; nt < 4; nt++)
            #pragma unroll
            for (int r = 0; r < 4; r++) acc[mt][nt][r] = 0.f;

    const int a_row = tid >> 3;
    const int a_kc  = (tid & 7) * 4;
    const int w_k   = tid >> 4;
    const int w_n4  = (tid & 15) * 4;

    float4 av[4], wv[2];

    auto load_regs = [&](int k0) {
        #pragma unroll
        for (int p = 0; p < 4; p++) {
            const int mg = m0 + a_row + 32 * p;
            if (D.ashift) {
                if ((mg & 511) == 0)
                    av[p] = make_float4(0.f, 0.f, 0.f, 0.f);
                else
                    av[p] = *(const float4*)(D.A + (size_t)(mg - 1) * D.lda + D.aoff + k0 + a_kc);
            } else {
                av[p] = *(const float4*)(D.A + (size_t)mg * D.lda + D.aoff + k0 + a_kc);
            }
        }
        #pragma unroll
        for (int p = 0; p < 2; p++)
            wv[p] = *(const float4*)(D.W + (size_t)(k0 + w_k + 16 * p) * D.ldw + D.woff + n0 + w_n4);
    };

    auto store_tiles = [&](u16* As, u16* Ws) {
        #pragma unroll
        for (int p = 0; p < 4; p++) {
            const int m = a_row + 32 * p;
            float hx, lx, hy, ly, hz, lz, hw, lw;
            split_bf16(av[p].x, hx, lx); split_bf16(av[p].y, hy, ly);
            split_bf16(av[p].z, hz, lz); split_bf16(av[p].w, hw, lw);
            *(u64*)&As[(size_t)m * GS_STRIDE + a_kc]         = pack4_bf16(hx, hy, hz, hw);
            *(u64*)&As[(size_t)(128 + m) * GS_STRIDE + a_kc] = pack4_bf16(lx, ly, lz, lw);
        }
        #pragma unroll
        for (int p = 0; p < 2; p++) {
            const int k = w_k + 16 * p;
            float h0, l0, h1, l1, h2, l2, h3, l3;
            split_bf16(wv[p].x, h0, l0); split_bf16(wv[p].y, h1, l1);
            split_bf16(wv[p].z, h2, l2); split_bf16(wv[p].w, h3, l3);
            *(u64*)&Ws[(size_t)k * GW_STRIDE + w_n4]        = pack4_bf16(h0, h1, h2, h3);
            *(u64*)&Ws[(size_t)(32 + k) * GW_STRIDE + w_n4] = pack4_bf16(l0, l1, l2, l3);
        }
    };

    auto do_mma = [&](const u16* As, const u16* Ws) {
        #pragma unroll
        for (int kk = 0; kk < 2; kk++) {
            u32 afr[2][2][4];
            #pragma unroll
            for (int s = 0; s < 2; s++)
                #pragma unroll
                for (int mt = 0; mt < 2; mt++)
                    ldsm4(afr[s][mt],
                          smaddr(&As[(size_t)(s * 128 + warp_m * 32 + mt * 16 + l15) * GS_STRIDE
                                     + kk * 16 + ka8]));
            u32 bfr[2][4][2];
            #pragma unroll
            for (int s = 0; s < 2; s++)
                #pragma unroll
                for (int ntp = 0; ntp < 2; ntp++) {
                    u32 t[4];
                    ldsm4t(t, smaddr(&Ws[(size_t)(s * 32 + kk * 16 + l7 + wk8) * GW_STRIDE
                                         + warp_n * 32 + ntp * 16 + wn8]));
                    bfr[s][2 * ntp][0]     = t[0]; bfr[s][2 * ntp][1]     = t[1];
                    bfr[s][2 * ntp + 1][0] = t[2]; bfr[s][2 * ntp + 1][1] = t[3];
                }
            #pragma unroll
            for (int mt = 0; mt < 2; mt++)
                #pragma unroll
                for (int nt = 0; nt < 4; nt++) {
                    mma_bf16(acc[mt][nt], afr[0][mt][0], afr[0][mt][1], afr[0][mt][2], afr[0][mt][3],
                             bfr[0][nt][0], bfr[0][nt][1]);
                    mma_bf16(acc[mt][nt], afr[0][mt][0], afr[0][mt][1], afr[0][mt][2], afr[0][mt][3],
                             bfr[1][nt][0], bfr[1][nt][1]);
                    mma_bf16(acc[mt][nt], afr[1][mt][0], afr[1][mt][1], afr[1][mt][2], afr[1][mt][3],
                             bfr[0][nt][0], bfr[0][nt][1]);
                }
        }
    };

    load_regs(0);
    store_tiles(smg, smg + G_ABUF);
    __syncthreads();

    const int nk = D.K >> 5;
    for (int ki = 0; ki < nk; ki++) {
        const int cur = ki & 1;
        const bool has_next = (ki + 1) < nk;
        if (has_next) load_regs((ki + 1) * 32);
        do_mma(smg + cur * G_BUF, smg + cur * G_BUF + G_ABUF);
        if (has_next) store_tiles(smg + (1 - cur) * G_BUF, smg + (1 - cur) * G_BUF + G_ABUF);
        __syncthreads();
    }

    #pragma unroll
    for (int mt = 0; mt < 2; mt++) {
        #pragma unroll
        for (int nt = 0; nt < 4; nt++) {
            const int m = m0 + warp_m * 32 + mt * 16 + g;
            const int n = n0 + warp_n * 32 + nt * 8 + tg * 2;
            const float bb0 = D.bias[n], bb1 = D.bias[n + 1];
            float v[4] = {acc[mt][nt][0] + bb0, acc[mt][nt][1] + bb1,
                          acc[mt][nt][2] + bb0, acc[mt][nt][3] + bb1};
            if (D.act == 1) {
                #pragma unroll
                for (int r = 0; r < 4; r++) {
                    float x = v[r];
                    float u = 0.7978845608028654f * (x + 0.044715f * x * x * x);
                    v[r] = 0.5f * x * (1.0f + tanhf(u));
                }
            }
            *(float2*)(D.C + (size_t)m * D.ldc + D.coff + n)       = make_float2(v[0], v[1]);
            *(float2*)(D.C + (size_t)(m + 8) * D.ldc + D.coff + n) = make_float2(v[2], v[3]);
        }
    }
}

// ---------------------------------------------------------------------------
// Batched flash attention, tensor cores + LDSM. V stored row-major; its
// transpose happens inside ldmatrix.trans. 64 q-rows/CTA, 4 warps, 128 thr.
// ---------------------------------------------------------------------------
#define AD_MAX 4
struct AttnDesc {
    const float *Q, *K, *V;
    float *O;
    int ldq, qoff, ldk, koff, ldv, voff, ldo, ooff, Tq, Tk, nbx, blk0;
};
struct AttnBatch { AttnDesc d[AD_MAX]; int n; };

#define AT_STRIDE 72
#define SMEM_ATTN_MMA (3 * 128 * AT_STRIDE * 2)

__global__ __launch_bounds__(128) void attn_batch_kernel(AttnBatch batch)
{
    extern __shared__ __align__(16) u16 smu[];
    u16 (*Qs)[AT_STRIDE] = (u16(*)[AT_STRIDE])smu;   // [row][dim], hi 0-63 / lo 64-127
    u16 (*Ks)[AT_STRIDE] = Qs + 128;                  // [key][dim], hi/lo
    u16 (*Vr)[AT_STRIDE] = Ks + 128;                  // [key][dim], hi/lo (row-major!)

    int pi = 0;
    #pragma unroll
    for (int i = 1; i < AD_MAX; i++)
        if (i < batch.n && (int)blockIdx.x >= batch.d[i].blk0) pi = i;
    const AttnDesc D = batch.d[pi];
    const int lb = blockIdx.x - D.blk0;
    const int qt = lb % D.nbx;
    const int h  = (lb / D.nbx) % H_;
    const int b  = lb / (D.nbx * H_);

    const float scale = 0.125f;
    const int tid  = threadIdx.x;
    const int lane = tid & 31;
    const int warp = tid >> 5;
    const int g  = lane >> 2;
    const int tg = lane & 3;
    const int mrow = warp * 16;

    // LDSM lane-address components
    const int l15 = lane & 15;
    const int l7  = lane & 7;
    const int qc8 = (lane >> 4) * 8;        // Q A-frag: col offset (m2,m3)
    const int kk8 = (lane >> 4) * 8;        // K B-frag: key offset (m2,m3)
    const int kd8 = ((lane >> 3) & 1) * 8;  // K B-frag: dim offset (m1,m3)
    const int vk8 = ((lane >> 3) & 1) * 8;  // V B-frag(trans): key offset (m1,m3)
    const int vd8 = (lane >> 4) * 8;        // V B-frag(trans): dim offset (m2,m3)

    const float* Qb = D.Q + (size_t)(b * D.Tq + qt * 64) * D.ldq + D.qoff + h * HD_;
    const float* Kb = D.K + (size_t)(b * D.Tk) * D.ldk + D.koff + h * HD_;
    const float* Vb = D.V + (size_t)(b * D.Tk) * D.ldv + D.voff + h * HD_;

    for (int e = tid; e < 64 * 16; e += 128) {
        const int r = e >> 4, c = (e & 15) * 4;
        float4 q4 = *(const float4*)(Qb + (size_t)r * D.ldq + c);
        float h0, l0, h1, l1, h2, l2, h3, l3;
        split_bf16(q4.x * scale, h0, l0); split_bf16(q4.y * scale, h1, l1);
        split_bf16(q4.z * scale, h2, l2); split_bf16(q4.w * scale, h3, l3);
        *(u64*)&Qs[r][c]      = pack4_bf16(h0, h1, h2, h3);
        *(u64*)&Qs[64 + r][c] = pack4_bf16(l0, l1, l2, l3);
    }

    float acc[8][4];
    #pragma unroll
    for (int nt = 0; nt < 8; nt++)
        #pragma unroll
        for (int r = 0; r < 4; r++) acc[nt][r] = 0.f;
    float mx0 = -1e30f, mx1 = -1e30f, lsum0 = 0.f, lsum1 = 0.f;

    for (int kt = 0; kt < D.Tk; kt += 64) {
        __syncthreads();
        for (int e = tid; e < 64 * 16; e += 128) {
            const int r = e >> 4, c = (e & 15) * 4;
            float4 k4 = *(const float4*)(Kb + (size_t)(kt + r) * D.ldk + c);
            float h0, l0, h1, l1, h2, l2, h3, l3;
            split_bf16(k4.x, h0, l0); split_bf16(k4.y, h1, l1);
            split_bf16(k4.z, h2, l2); split_bf16(k4.w, h3, l3);
            *(u64*)&Ks[r][c]      = pack4_bf16(h0, h1, h2, h3);
            *(u64*)&Ks[64 + r][c] = pack4_bf16(l0, l1, l2, l3);
            float4 v4 = *(const float4*)(Vb + (size_t)(kt + r) * D.ldv + c);
            split_bf16(v4.x, h0, l0); split_bf16(v4.y, h1, l1);
            split_bf16(v4.z, h2, l2); split_bf16(v4.w, h3, l3);
            *(u64*)&Vr[r][c]      = pack4_bf16(h0, h1, h2, h3);
            *(u64*)&Vr[64 + r][c] = pack4_bf16(l0, l1, l2, l3);
        }
        __syncthreads();

        // ---- S = Q K^T (hi*hi + hi*lo + lo*hi) ----
        float s[8][4];
        #pragma unroll
        for (int nt = 0; nt < 8; nt++)
            #pragma unroll
            for (int r = 0; r < 4; r++) s[nt][r] = 0.f;

        #pragma unroll
        for (int kc = 0; kc < 4; kc++) {
            u32 ah[4], al[4];
            ldsm4(ah, smaddr(&Qs[mrow + l15][kc * 16 + qc8]));
            ldsm4(al, smaddr(&Qs[64 + mrow + l15][kc * 16 + qc8]));
            #pragma unroll
            for (int ntp = 0; ntp < 4; ntp++) {
                u32 kh[4], kl[4];
                ldsm4(kh, smaddr(&Ks[ntp * 16 + l7 + kk8][kc * 16 + kd8]));
                ldsm4(kl, smaddr(&Ks[64 + ntp * 16 + l7 + kk8][kc * 16 + kd8]));
                mma_bf16(s[2 * ntp],     ah[0], ah[1], ah[2], ah[3], kh[0], kh[1]);
                mma_bf16(s[2 * ntp],     ah[0], ah[1], ah[2], ah[3], kl[0], kl[1]);
                mma_bf16(s[2 * ntp],     al[0], al[1], al[2], al[3], kh[0], kh[1]);
                mma_bf16(s[2 * ntp + 1], ah[0], ah[1], ah[2], ah[3], kh[2], kh[3]);
                mma_bf16(s[2 * ntp + 1], ah[0], ah[1], ah[2], ah[3], kl[2], kl[3]);
                mma_bf16(s[2 * ntp + 1], al[0], al[1], al[2], al[3], kh[2], kh[3]);
            }
        }

        // ---- online softmax ----
        float rm0 = -1e30f, rm1 = -1e30f;
        #pragma unroll
        for (int nt = 0; nt < 8; nt++) {
            rm0 = fmaxf(rm0, fmaxf(s[nt][0], s[nt][1]));
            rm1 = fmaxf(rm1, fmaxf(s[nt][2], s[nt][3]));
        }
        rm0 = fmaxf(rm0, __shfl_xor_sync(0xffffffffu, rm0, 1));
        rm0 = fmaxf(rm0, __shfl_xor_sync(0xffffffffu, rm0, 2));
        rm1 = fmaxf(rm1, __shfl_xor_sync(0xffffffffu, rm1, 1));
        rm1 = fmaxf(rm1, __shfl_xor_sync(0xffffffffu, rm1, 2));

        const float mn0 = fmaxf(mx0, rm0);
        const float mn1 = fmaxf(mx1, rm1);
        const float corr0 = __expf(mx0 - mn0);
        const float corr1 = __expf(mx1 - mn1);
        float rs0 = 0.f, rs1 = 0.f;
        #pragma unroll
        for (int nt = 0; nt < 8; nt++) {
            s[nt][0] = __expf(s[nt][0] - mn0); rs0 += s[nt][0];
            s[nt][1] = __expf(s[nt][1] - mn0); rs0 += s[nt][1];
            s[nt][2] = __expf(s[nt][2] - mn1); rs1 += s[nt][2];
            s[nt][3] = __expf(s[nt][3] - mn1); rs1 += s[nt][3];
        }
        rs0 += __shfl_xor_sync(0xffffffffu, rs0, 1);
        rs0 += __shfl_xor_sync(0xffffffffu, rs0, 2);
        rs1 += __shfl_xor_sync(0xffffffffu, rs1, 1);
        rs1 += __shfl_xor_sync(0xffffffffu, rs1, 2);
        lsum0 = lsum0 * corr0 + rs0; mx0 = mn0;
        lsum1 = lsum1 * corr1 + rs1; mx1 = mn1;
        #pragma unroll
        for (int nt = 0; nt < 8; nt++) {
            acc[nt][0] *= corr0; acc[nt][1] *= corr0;
            acc[nt][2] *= corr1; acc[nt][3] *= corr1;
        }

        // ---- O += P V ----
        #pragma unroll
        for (int kc = 0; kc < 4; kc++) {
            const int j0 = 2 * kc, j1 = 2 * kc + 1;
            float ph[8], pl[8];
            #pragma unroll
            for (int r = 0; r < 4; r++) { split_bf16(s[j0][r], ph[r],     pl[r]); }
            #pragma unroll
            for (int r = 0; r < 4; r++) { split_bf16(s[j1][r], ph[4 + r], pl[4 + r]); }
            u32 pah[4], pal[4];
            pah[0] = pack_bf16(ph[0], ph[1]); pal[0] = pack_bf16(pl[0], pl[1]);
            pah[1] = pack_bf16(ph[2], ph[3]); pal[1] = pack_bf16(pl[2], pl[3]);
            pah[2] = pack_bf16(ph[4], ph[5]); pal[2] = pack_bf16(pl[4], pl[5]);
            pah[3] = pack_bf16(ph[6], ph[7]); pal[3] = pack_bf16(pl[6], pl[7]);

            #pragma unroll
            for (int ntp = 0; ntp < 4; ntp++) {
                u32 vh[4], vl[4];
                ldsm4t(vh, smaddr(&Vr[kc * 16 + l7 + vk8][ntp * 16 + vd8]));
                ldsm4t(vl, smaddr(&Vr[64 + kc * 16 + l7 + vk8][ntp * 16 + vd8]));
                mma_bf16(acc[2 * ntp],     pah[0], pah[1], pah[2], pah[3], vh[0], vh[1]);
                mma_bf16(acc[2 * ntp],     pah[0], pah[1], pah[2], pah[3], vl[0], vl[1]);
                mma_bf16(acc[2 * ntp],     pal[0], pal[1], pal[2], pal[3], vh[0], vh[1]);
                mma_bf16(acc[2 * ntp + 1], pah[0], pah[1], pah[2], pah[3], vh[2], vh[3]);
                mma_bf16(acc[2 * ntp + 1], pah[0], pah[1], pah[2], pah[3], vl[2], vl[3]);
                mma_bf16(acc[2 * ntp + 1], pal[0], pal[1], pal[2], pal[3], vh[2], vh[3]);
            }
        }
    }

    const float inv0 = 1.0f / lsum0;
    const float inv1 = 1.0f / lsum1;
    float* Ob = D.O + (size_t)(b * D.Tq + qt * 64 + mrow) * D.ldo + D.ooff + h * HD_;
    #pragma unroll
    for (int nt = 0; nt < 8; nt++) {
        const int col = nt * 8 + 2 * tg;
        *(float2*)(Ob + (size_t)g * D.ldo + col) =
            make_float2(acc[nt][0] * inv0, acc[nt][1] * inv0);
        *(float2*)(Ob + (size_t)(g + 8) * D.ldo + col) =
            make_float2(acc[nt][2] * inv1, acc[nt][3] * inv1);
    }
}

// ---------------------------------------------------------------------------
// Host orchestration: 5 launches
// ---------------------------------------------------------------------------
static inline GemmDesc mk_gemm(const float* A, int lda, int aoff,
                               const float* W, int ldw, int woff,
                               const float* bias, float* C, int ldc, int coff,
                               int M, int N, int K, int act, int ashift,
                               int& blk_cursor)
{
    GemmDesc d;
    d.A = A; d.W = W; d.bias = bias; d.C = C;
    d.lda = lda; d.aoff = aoff; d.ldw = ldw; d.woff = woff;
    d.ldc = ldc; d.coff = coff; d.K = K; d.act = act; d.ashift = ashift;
    d.nbx = N / 64; d.blk0 = blk_cursor;
    blk_cursor += (N / 64) * (M / 128);
    return d;
}

static inline AttnDesc mk_attn(const float* Q, int ldq, int qoff,
                               const float* K, int ldk, int koff,
                               const float* V, int ldv, int voff,
                               float* O, int ldo, int ooff,
                               int Tq, int Tk, int& blk_cursor)
{
    AttnDesc d;
    d.Q = Q; d.K = K; d.V = V; d.O = O;
    d.ldq = ldq; d.qoff = qoff; d.ldk = ldk; d.koff = koff;
    d.ldv = ldv; d.voff = voff; d.ldo = ldo; d.ooff = ooff;
    d.Tq = Tq; d.Tk = Tk; d.nbx = Tq / 64; d.blk0 = blk_cursor;
    blk_cursor += (Tq / 64) * H_ * B_;
    return d;
}

extern "C" void kernel_launch(void* const* d_in, const int* in_sizes, int n_in,
                              void* d_out, int out_size)
{
    (void)in_sizes; (void)n_in; (void)out_size;

    const float* x_fast      = (const float*)d_in[0];
    const float* x_slow      = (const float*)d_in[1];
    const float* fself_wqkv  = (const float*)d_in[2];
    const float* fself_bqkv  = (const float*)d_in[3];
    const float* fself_wo    = (const float*)d_in[4];
    const float* fself_bo    = (const float*)d_in[5];
    const float* fcross_wqkv = (const float*)d_in[6];
    const float* fcross_bqkv = (const float*)d_in[7];
    const float* fcross_wo   = (const float*)d_in[8];
    const float* fcross_bo   = (const float*)d_in[9];
    const float* sself_wqkv  = (const float*)d_in[10];
    const float* sself_bqkv  = (const float*)d_in[11];
    const float* sself_wo    = (const float*)d_in[12];
    const float* sself_bo    = (const float*)d_in[13];
    const float* scross_wqkv = (const float*)d_in[14];
    const float* scross_bqkv = (const float*)d_in[15];
    const float* scross_wo   = (const float*)d_in[16];
    const float* scross_bo   = (const float*)d_in[17];
    const float* lift_w      = (const float*)d_in[18];
    const float* lift_b      = (const float*)d_in[19];
    const float* pool_w1     = (const float*)d_in[20];
    const float* pool_b1     = (const float*)d_in[21];
    const float* pool_w2     = (const float*)d_in[22];
    const float* pool_b2     = (const float*)d_in[23];

    float* out = (float*)d_out;
    float* zf = out;
    float* zs = out + (size_t)B_ * LF_ * 1024;

    float* S0 = nullptr;
    cudaGetSymbolAddress((void**)&S0, g_scratch);
    float* y     = S0 + O_Y;
    float* qkv_f = S0 + O_QKV_F;
    float* q_fc  = S0 + O_Q_FC;
    float* kv_fc = S0 + O_KV_FC;
    float* o1    = S0 + O_O1;
    float* o2    = S0 + O_O2;
    float* h1    = S0 + O_H1;
    float* s     = S0 + O_S;
    float* qkv_s = S0 + O_QKV_S;
    float* q_sc  = S0 + O_Q_SC;
    float* kv_sc = S0 + O_KV_SC;
    float* o3    = S0 + O_O3;
    float* o4    = S0 + O_O4;

    cudaFuncSetAttribute(gemm_batch_kernel,
                         cudaFuncAttributeMaxDynamicSharedMemorySize, SMEM_GEMM);
    cudaFuncSetAttribute(attn_batch_kernel,
                         cudaFuncAttributeMaxDynamicSharedMemorySize, SMEM_ATTN_MMA);

    // ---- L1: input-only GEMMs ----
    {
        GemmBatch gb; int cur = 0;
        gb.d[0] = mk_gemm(x_fast, 1024, 0,   fself_wqkv, 1536, 0, fself_bqkv,        qkv_f, 1536, 0, 4096, 1536, 512, 0, 0, cur);
        gb.d[1] = mk_gemm(x_fast, 4096, 0,   pool_w1,    2048, 0, pool_b1,           h1,    2048, 0, 1024, POOLH, 4096, 1, 0, cur);
        gb.d[2] = mk_gemm(x_fast, 1024, 512, fcross_wqkv, 1536, 0, fcross_bqkv,      q_fc,  512,  0, 4096, 512,  512, 0, 0, cur);
        gb.d[3] = mk_gemm(x_slow, 1024, 0,   lift_w,     512,  0, lift_b,            y,     512,  0, 1024, 512,  1024, 0, 0, cur);
        gb.d[4] = mk_gemm(x_slow, 1024, 0,   sself_wqkv, 1536, 0, sself_bqkv,        qkv_s, 1536, 0, 1024, 1536, 512, 0, 0, cur);
        gb.d[5] = mk_gemm(x_slow, 1024, 512, scross_wqkv, 1536, 0, scross_bqkv,      q_sc,  512,  0, 1024, 512,  512, 0, 0, cur);
        gb.n = 6;
        gemm_batch_kernel<<<cur, 256, SMEM_GEMM>>>(gb);
    }
    // ---- L2: kv_fc (needs y) + pool2 (needs h1) ----
    {
        GemmBatch gb; int cur = 0;
        gb.d[0] = mk_gemm(y,  512,  0, fcross_wqkv, 1536, 512, fcross_bqkv + 512, kv_fc, 1024, 0, 1024, 1024, 512,  0, 0, cur);
        gb.d[1] = mk_gemm(h1, 2048, 0, pool_w2,     512,  0,   pool_b2,           s,     512,  0, 1024, 512,  2048, 0, 0, cur);
        gb.n = 2;
        gemm_batch_kernel<<<cur, 256, SMEM_GEMM>>>(gb);
    }
    // ---- L3: kv_sc on shifted s (shift folded into A-load) ----
    {
        GemmBatch gb; int cur = 0;
        gb.d[0] = mk_gemm(s, 512, 0, scross_wqkv, 1536, 512, scross_bqkv + 512, kv_sc, 1024, 0, 1024, 1024, 512, 0, 1, cur);
        gb.n = 1;
        gemm_batch_kernel<<<cur, 256, SMEM_GEMM>>>(gb);
    }
    // ---- L4: all four attentions ----
    {
        AttnBatch ab; int cur = 0;
        ab.d[0] = mk_attn(qkv_f, 1536, 0, qkv_f, 1536, 512, qkv_f, 1536, 1024, o1, 512, 0, LF_, LF_, cur);
        ab.d[1] = mk_attn(q_fc,  512,  0, kv_fc, 1024, 0,   kv_fc, 1024, 512,  o2, 512, 0, LF_, TS_, cur);
        ab.d[2] = mk_attn(qkv_s, 1536, 0, qkv_s, 1536, 512, qkv_s, 1536, 1024, o3, 512, 0, TS_, TS_, cur);
        ab.d[3] = mk_attn(q_sc,  512,  0, kv_sc, 1024, 0,   kv_sc, 1024, 512,  o4, 512, 0, TS_, TS_, cur);
        ab.n = 4;
        attn_batch_kernel<<<cur, 128, SMEM_ATTN_MMA>>>(ab);
    }
    // ---- L5: all four out-projections ----
    {
        GemmBatch gb; int cur = 0;
        gb.d[0] = mk_gemm(o1, 512, 0, fself_wo,  512, 0, fself_bo,  zf, 1024, 0,   4096, 512, 512, 0, 0, cur);
        gb.d[1] = mk_gemm(o2, 512, 0, fcross_wo, 512, 0, fcross_bo, zf, 1024, 512, 4096, 512, 512, 0, 0, cur);
        gb.d[2] = mk_gemm(o3, 512, 0, sself_wo,  512, 0, sself_bo,  zs, 1024, 0,   1024, 512, 512, 0, 0, cur);
        gb.d[3] = mk_gemm(o4, 512, 0, scross_wo, 512, 0, scross_bo, zs, 1024, 512, 1024, 512, 512, 0, 0, cur);
        gb.n = 4;
        gemm_batch_kernel<<<cur, 256, SMEM_GEMM>>>(gb);
    }
}